// round 13
// baseline (speedup 1.0000x reference)
#include <cuda_runtime.h>
#include <cuda_fp16.h>
#include <cstdint>
#include <cstddef>

#define DI __device__ __forceinline__

#define BATCH 1024
#define NF    32
#define NPAIR 496
#define T_LD  1984
#define X_LD  2048
#define HALFK 31744
#define KTOT  63488
#define H1    1024
#define H2    512
#define S0    16                 // fc0 split-K
#define S1    8                  // fc1 split-K

// GEMM tile: BM=64, BN=256, BK=64, 128 threads (4 warps, warp tile 64x64).
// fp16 operands in smem, row stride 72 halves (144B) -> conflict-free scalar LDS
// (bank = 4*mlane + klane mod 32, all distinct). 2-stage cp.async pipeline.
#define SROWH 72
#define SROWB 144
#define ATILE_B (64*SROWB)          // 9216
#define BTILE_B (256*SROWB)         // 36864
#define STAGE_B (ATILE_B+BTILE_B)   // 46080
#define SMEM_DYN (2*STAGE_B)        // 92160

__device__ float  g_x2[BATCH*X_LD];
__device__ float  g_T[2*BATCH*T_LD];
__device__ __half g_feat[(size_t)BATCH*KTOT];   // materialized bilinear features (130MB)
__device__ __half g_w0h[(size_t)H1*KTOT];       // fp16 fc0 weights (130MB)
__device__ __half g_w1h[H2*H1];
__device__ float  g_part0[(size_t)S0*BATCH*H1]; // 64MB
__device__ __half g_h0h[BATCH*H1];
__device__ float  g_part1[(size_t)S1*BATCH*H2]; // 16MB
__device__ float  g_h1[BATCH*H2];
__device__ int    g_pi[NPAIR];
__device__ int    g_pj[NPAIR];

DI uint32_t smem_u32(const void* p) {
    uint32_t a;
    asm("{ .reg .u64 t; cvta.to.shared.u64 t, %1; cvt.u32.u64 %0, t; }" : "=r"(a) : "l"(p));
    return a;
}

DI void cp_async16(uint32_t dst, const void* src) {
    asm volatile("cp.async.cg.shared.global [%0], [%1], 16;" :: "r"(dst), "l"(src));
}
#define CP_COMMIT() asm volatile("cp.async.commit_group;" ::: "memory")
#define CP_WAIT0()  asm volatile("cp.async.wait_group 0;" ::: "memory")

DI void mma_f16(float* d, const uint32_t* a, const uint32_t* b) {
    asm volatile(
        "mma.sync.aligned.m16n8k16.row.col.f32.f16.f16.f32 "
        "{%0,%1,%2,%3}, {%4,%5,%6,%7}, {%8,%9}, {%0,%1,%2,%3};"
        : "+f"(d[0]), "+f"(d[1]), "+f"(d[2]), "+f"(d[3])
        : "r"(a[0]), "r"(a[1]), "r"(a[2]), "r"(a[3]), "r"(b[0]), "r"(b[1]));
}

DI uint32_t pack_h2(float a, float b) {
    __half2 h = __floats2half2_rn(a, b);
    return *(uint32_t*)&h;
}

// ---------------- SE block (+pair-table init in the extra block) ----------------
__global__ void __launch_bounds__(256) se_kernel(const float* __restrict__ x,
                                                 const float* __restrict__ w1,
                                                 const float* __restrict__ w2) {
    if (blockIdx.x == BATCH) {
        if (threadIdx.x == 0) {
            int idx = 0;
            for (int i = 0; i < NF - 1; i++)
                for (int j = i + 1; j < NF; j++) { g_pi[idx] = i; g_pj[idx] = j; idx++; }
        }
        return;
    }
    __shared__ float xs[X_LD];
    __shared__ float Zs[NF], A1s[4], A2s[NF];
    int b = blockIdx.x, tid = threadIdx.x;
    const float4* xr = (const float4*)(x + (size_t)b * X_LD);
    float4* xs4 = (float4*)xs;
    xs4[tid] = xr[tid];
    xs4[tid + 256] = xr[tid + 256];
    __syncthreads();
    int wid = tid >> 5, lane = tid & 31;
    #pragma unroll
    for (int ff = 0; ff < 4; ff++) {
        int f = wid * 4 + ff;
        float v = xs[f * 64 + lane] + xs[f * 64 + 32 + lane];
        #pragma unroll
        for (int o = 16; o; o >>= 1) v += __shfl_xor_sync(0xffffffffu, v, o);
        if (lane == 0) Zs[f] = v * (1.0f / 64.0f);
    }
    __syncthreads();
    if (tid < 4) {
        float a = 0.f;
        #pragma unroll
        for (int f = 0; f < NF; f++) a += Zs[f] * w1[tid * NF + f];
        A1s[tid] = fmaxf(a, 0.0f);
    }
    __syncthreads();
    if (tid < NF) {
        float a = 0.f;
        #pragma unroll
        for (int r = 0; r < 4; r++) a += A1s[r] * w2[tid * 4 + r];
        A2s[tid] = 1.0f / (1.0f + expf(-a));
    }
    __syncthreads();
    float4* o4 = (float4*)(g_x2 + (size_t)b * X_LD);
    #pragma unroll
    for (int q = 0; q < 2; q++) {
        int i = tid + q * 256;
        float4 v = xs4[i];
        float sc = A2s[i >> 4];
        v.x *= sc; v.y *= sc; v.z *= sc; v.w *= sc;
        o4[i] = v;
    }
}

// t[v][b][i*64+o] = sum_e feats_v[b,i,e] * W_v[i,o,e]
__global__ void __launch_bounds__(256) tfield_kernel(const float* __restrict__ x,
                                                     const float* __restrict__ W1,
                                                     const float* __restrict__ W2) {
    __shared__ float Ws[64 * 68];
    __shared__ float xs[16 * 68];
    __shared__ float ts[1024];
    int v = blockIdx.z, fi = blockIdx.x, b0 = blockIdx.y * 16;
    int tid = threadIdx.x;
    const float* W = (v ? W2 : W1) + (size_t)fi * 4096;
    for (int idx = tid; idx < 4096; idx += 256)
        Ws[(idx >> 6) * 68 + (idx & 63)] = W[idx];
    const float* xsrc = (v ? g_x2 : x) + (size_t)b0 * X_LD + fi * 64;
    for (int idx = tid; idx < 1024; idx += 256)
        xs[(idx >> 6) * 68 + (idx & 63)] = xsrc[(size_t)(idx >> 6) * X_LD + (idx & 63)];
    __syncthreads();
    int o = tid >> 2, bg = tid & 3;
    float s0 = 0.f, s1 = 0.f, s2 = 0.f, s3 = 0.f;
    const float4* wrow = (const float4*)(Ws + o * 68);
    #pragma unroll
    for (int e4 = 0; e4 < 16; e4++) {
        float4 wv = wrow[e4];
        float4 a0 = *(const float4*)(xs + (bg * 4 + 0) * 68 + e4 * 4);
        float4 a1 = *(const float4*)(xs + (bg * 4 + 1) * 68 + e4 * 4);
        float4 a2 = *(const float4*)(xs + (bg * 4 + 2) * 68 + e4 * 4);
        float4 a3 = *(const float4*)(xs + (bg * 4 + 3) * 68 + e4 * 4);
        s0 += wv.x*a0.x + wv.y*a0.y + wv.z*a0.z + wv.w*a0.w;
        s1 += wv.x*a1.x + wv.y*a1.y + wv.z*a1.z + wv.w*a1.w;
        s2 += wv.x*a2.x + wv.y*a2.y + wv.z*a2.z + wv.w*a2.w;
        s3 += wv.x*a3.x + wv.y*a3.y + wv.z*a3.z + wv.w*a3.w;
    }
    ts[(bg * 4 + 0) * 64 + o] = s0;
    ts[(bg * 4 + 1) * 64 + o] = s1;
    ts[(bg * 4 + 2) * 64 + o] = s2;
    ts[(bg * 4 + 3) * 64 + o] = s3;
    __syncthreads();
    float* trow = g_T + (size_t)v * (BATCH * T_LD);
    for (int idx = tid; idx < 1024; idx += 256)
        trow[(size_t)(b0 + (idx >> 6)) * T_LD + fi * 64 + (idx & 63)] = ts[idx];
}

// ---------------- fused prep: featgen + fc0 weight f2h + fc1 weight f2h ----------------
#define PREP_FEAT   31744
#define PREP_W0     63488
#define PREP_W1B    512
__global__ void __launch_bounds__(256) prep_kernel(const float* __restrict__ x,
                                                   const float* __restrict__ fc0w,
                                                   const float* __restrict__ fc1w) {
    int blk = blockIdx.x;
    int tid = threadIdx.x;
    if (blk < PREP_FEAT) {
        int p = blk % NPAIR;
        int rest = blk / NPAIR;        // 0..63
        int b0 = (rest & 31) * 32;
        int v = rest >> 5;
        int r = tid >> 3, ec = (tid & 7) * 8;
        int ip = g_pi[p], jp = g_pj[p];
        int b = b0 + r;
        const float* tb = g_T + (size_t)v * (BATCH * T_LD) + (size_t)b * T_LD + ip * 64 + ec;
        const float* xb = (v ? g_x2 : x) + (size_t)b * X_LD + jp * 64 + ec;
        float4 t0 = *(const float4*)tb, t1 = *(const float4*)(tb + 4);
        float4 x0 = *(const float4*)xb, x1 = *(const float4*)(xb + 4);
        uint4 o;
        o.x = pack_h2(t0.x * x0.x, t0.y * x0.y);
        o.y = pack_h2(t0.z * x0.z, t0.w * x0.w);
        o.z = pack_h2(t1.x * x1.x, t1.y * x1.y);
        o.w = pack_h2(t1.z * x1.z, t1.w * x1.w);
        *(uint4*)(g_feat + (size_t)b * KTOT + v * HALFK + p * 64 + ec) = o;
    } else if (blk < PREP_FEAT + PREP_W0) {
        int i = (blk - PREP_FEAT) * 256 + tid;
        float4 v = ((const float4*)fc0w)[i];
        uint2 o;
        o.x = pack_h2(v.x, v.y);
        o.y = pack_h2(v.z, v.w);
        ((uint2*)g_w0h)[i] = o;
    } else {
        int i = (blk - PREP_FEAT - PREP_W0) * 256 + tid;
        float4 v = ((const float4*)fc1w)[i];
        uint2 o;
        o.x = pack_h2(v.x, v.y);
        o.y = pack_h2(v.z, v.w);
        ((uint2*)g_w1h)[i] = o;
    }
}

// ---------------- mma.sync fp16 GEMM (BM=64, BN=256, BK=64, warp tile 64x64) ----------------
// C[m,n] = sum_k A[m,k] * W[n,k]; A, W fp16 row-major with row stride Ktot.
// 128 threads = 4 warps (warp-cols). CTA decode: mb fastest, then nb, then s.
__global__ void __launch_bounds__(128, 2) gemm_kernel(const __half* __restrict__ Ah,
                                                      const __half* __restrict__ Bw,
                                                      float* __restrict__ Cpart,
                                                      int Ntot, int Ktot, int S) {
    extern __shared__ char smc[];
    uint32_t smb = smem_u32(smc);
    int tid = threadIdx.x;
    int wc = tid >> 5, l = tid & 31;
    int nbn = Ntot >> 8;
    int mb = blockIdx.x % 16;
    int nb = (blockIdx.x / 16) % nbn;
    int s  = blockIdx.x / (16 * nbn);
    int m0 = mb * 64, n0 = nb * 256;
    int Kper = Ktot / S;
    int k_base = s * Kper;
    int ntiles = Kper >> 6;

    float acc[4][8][4];
    #pragma unroll
    for (int i = 0; i < 4; i++)
        #pragma unroll
        for (int j = 0; j < 8; j++)
            #pragma unroll
            for (int q = 0; q < 4; q++) acc[i][j][q] = 0.f;

    auto cp_tile = [&](int kg, int st) {
        uint32_t baseA = smb + st * STAGE_B;
        uint32_t baseB = baseA + ATILE_B;
        // A: 64 rows x 8 chunks = 512 chunks, 4 per thread
        #pragma unroll
        for (int it = 0; it < 4; it++) {
            int chunk = tid + it * 128;
            int r = chunk >> 3, ch = chunk & 7;
            cp_async16(baseA + r * SROWB + ch * 16,
                       Ah + (size_t)(m0 + r) * Ktot + kg + ch * 8);
        }
        // B: 256 rows x 8 chunks = 2048 chunks, 16 per thread
        #pragma unroll
        for (int it = 0; it < 16; it++) {
            int chunk = tid + it * 128;
            int r = chunk >> 3, ch = chunk & 7;
            cp_async16(baseB + r * SROWB + ch * 16,
                       Bw + (size_t)(n0 + r) * Ktot + kg + ch * 8);
        }
    };

    cp_tile(k_base, 0);
    CP_COMMIT();

    int mlane = l >> 2, klane = l & 3;
    for (int kt = 0; kt < ntiles; kt++) {
        int st = kt & 1;
        CP_WAIT0();
        __syncthreads();
        if (kt + 1 < ntiles) {
            cp_tile(k_base + ((kt + 1) << 6), st ^ 1);
            CP_COMMIT();
        }

        const uint32_t* uA = (const uint32_t*)(smc + st * STAGE_B);
        const uint32_t* uB = (const uint32_t*)(smc + st * STAGE_B + ATILE_B);
        #pragma unroll
        for (int ks = 0; ks < 4; ks++) {
            int kw = ks * 8 + klane;
            uint32_t afr[4][4], bfr[8][2];
            #pragma unroll
            for (int mf = 0; mf < 4; mf++) {
                int m = mf * 16 + mlane;
                afr[mf][0] = uA[m * 36 + kw];
                afr[mf][1] = uA[(m + 8) * 36 + kw];
                afr[mf][2] = uA[m * 36 + kw + 4];
                afr[mf][3] = uA[(m + 8) * 36 + kw + 4];
            }
            #pragma unroll
            for (int nf = 0; nf < 8; nf++) {
                int n = wc * 64 + nf * 8 + mlane;
                bfr[nf][0] = uB[n * 36 + kw];
                bfr[nf][1] = uB[n * 36 + kw + 4];
            }
            #pragma unroll
            for (int mf = 0; mf < 4; mf++)
                #pragma unroll
                for (int nf = 0; nf < 8; nf++)
                    mma_f16(acc[mf][nf], afr[mf], bfr[nf]);
        }
    }

    float* crow = Cpart + ((size_t)s * BATCH + m0) * Ntot + n0 + wc * 64;
    #pragma unroll
    for (int mf = 0; mf < 4; mf++) {
        int mm = mf * 16 + (l >> 2);
        #pragma unroll
        for (int nf = 0; nf < 8; nf++) {
            int nn = nf * 8 + (l & 3) * 2;
            *(float2*)(crow + (size_t)mm * Ntot + nn) = make_float2(acc[mf][nf][0], acc[mf][nf][1]);
            *(float2*)(crow + (size_t)(mm + 8) * Ntot + nn) = make_float2(acc[mf][nf][2], acc[mf][nf][3]);
        }
    }
}

// ---------------- reductions / final ----------------
__global__ void __launch_bounds__(256) reduce0_kernel(const float* __restrict__ bias) {
    int f = blockIdx.x * 256 + threadIdx.x;   // float4 index, 262144 total
    const float4* p = (const float4*)g_part0;
    float4 b = ((const float4*)bias)[f & 255];
    float sx = b.x, sy = b.y, sz = b.z, sw = b.w;
    #pragma unroll
    for (int i = 0; i < S0; i++) {
        float4 a = p[f + (size_t)i * 262144];
        sx += a.x; sy += a.y; sz += a.z; sw += a.w;
    }
    uint2 o;
    o.x = pack_h2(fmaxf(sx, 0.f), fmaxf(sy, 0.f));
    o.y = pack_h2(fmaxf(sz, 0.f), fmaxf(sw, 0.f));
    ((uint2*)g_h0h)[f] = o;
}

__global__ void __launch_bounds__(256) reduce1_kernel(const float* __restrict__ bias) {
    int f = blockIdx.x * 256 + threadIdx.x;   // float4 index, 131072 total
    const float4* p = (const float4*)g_part1;
    float4 b = ((const float4*)bias)[f & 127];
    float sx = b.x, sy = b.y, sz = b.z, sw = b.w;
    #pragma unroll
    for (int i = 0; i < S1; i++) {
        float4 a = p[f + (size_t)i * 131072];
        sx += a.x; sy += a.y; sz += a.z; sw += a.w;
    }
    float4 o;
    o.x = fmaxf(sx, 0.f); o.y = fmaxf(sy, 0.f);
    o.z = fmaxf(sz, 0.f); o.w = fmaxf(sw, 0.f);
    ((float4*)g_h1)[f] = o;
}

__global__ void __launch_bounds__(256) fc2_kernel(const float* __restrict__ w,
                                                  const float* __restrict__ bias,
                                                  float* __restrict__ out) {
    int wid = threadIdx.x >> 5, lane = threadIdx.x & 31;
    int row = blockIdx.x * 8 + wid;
    const float4* h = (const float4*)(g_h1 + (size_t)row * H2);
    const float4* wv = (const float4*)w;
    float s = 0.f;
    #pragma unroll
    for (int q = 0; q < 4; q++) {
        float4 a = h[lane + q * 32], b = wv[lane + q * 32];
        s += a.x * b.x + a.y * b.y + a.z * b.z + a.w * b.w;
    }
    #pragma unroll
    for (int o = 16; o; o >>= 1) s += __shfl_xor_sync(0xffffffffu, s, o);
    if (lane == 0) out[row] = 1.0f / (1.0f + expf(-(s + bias[0])));
}

// ---------------- launch ----------------
extern "C" void kernel_launch(void* const* d_in, const int* in_sizes, int n_in,
                              void* d_out, int out_size) {
    const float* x    = (const float*)d_in[0];
    const float* W1   = (const float*)d_in[1];
    const float* W2   = (const float*)d_in[2];
    const float* sw1  = (const float*)d_in[3];
    const float* sw2  = (const float*)d_in[4];
    const float* fc0w = (const float*)d_in[5];
    const float* fc0b = (const float*)d_in[6];
    const float* fc1w = (const float*)d_in[7];
    const float* fc1b = (const float*)d_in[8];
    const float* fc2w = (const float*)d_in[9];
    const float* fc2b = (const float*)d_in[10];
    float* out = (float*)d_out;

    __half* w0h;  cudaGetSymbolAddress((void**)&w0h, g_w0h);
    __half* w1h;  cudaGetSymbolAddress((void**)&w1h, g_w1h);
    __half* feat; cudaGetSymbolAddress((void**)&feat, g_feat);
    __half* h0h;  cudaGetSymbolAddress((void**)&h0h, g_h0h);
    float* part0; cudaGetSymbolAddress((void**)&part0, g_part0);
    float* part1; cudaGetSymbolAddress((void**)&part1, g_part1);

    cudaFuncSetAttribute(gemm_kernel, cudaFuncAttributeMaxDynamicSharedMemorySize, SMEM_DYN);

    se_kernel<<<BATCH + 1, 256>>>(x, sw1, sw2);                      // #1 (+pair init)
    tfield_kernel<<<dim3(31, BATCH / 16, 2), 256>>>(x, W1, W2);      // #2
    prep_kernel<<<PREP_FEAT + PREP_W0 + PREP_W1B, 256>>>(x, fc0w, fc1w); // #3
    gemm_kernel<<<16 * 4 * S0, 128, SMEM_DYN>>>(feat, w0h, part0, H1, KTOT, S0); // #4 <- profiled
    reduce0_kernel<<<1024, 256>>>(fc0b);
    gemm_kernel<<<16 * 2 * S1, 128, SMEM_DYN>>>(h0h, w1h, part1, H2, H1, S1);
    reduce1_kernel<<<512, 256>>>(fc1b);
    fc2_kernel<<<BATCH / 8, 256>>>(fc2w, fc2b, out);
}

// round 14
// speedup vs baseline: 1.3890x; 1.3890x over previous
#include <cuda_runtime.h>
#include <cuda_fp16.h>
#include <cstdint>
#include <cstddef>

#define DI __device__ __forceinline__

#define BATCH 1024
#define NF    32
#define NPAIR 496
#define T_LD  1984
#define X_LD  2048
#define HALFK 31744
#define KTOT  63488
#define H1    1024
#define H2    512
#define S0    32                 // fc0 split-K
#define S1    8                  // fc1 split-K

// GEMM tile: BM=128, BN=128, BK=64, 256 threads (8 warps: 2 warp-rows x 4 warp-cols,
// warp tile 64x32). fp16 operands in smem, row stride 72 halves (144B) -> conflict-free
// scalar LDS feed (bank = 4*mlane + klane mod 32, all distinct). 3-stage cp.async pipeline.
#define SROWH 72
#define SROWB 144
#define TBUFH_BYTES (128*SROWB)  // 18432
#define NSTAGE 3
#define SMEM_DYN (2*NSTAGE*TBUFH_BYTES) // 110592

__device__ float  g_x2[BATCH*X_LD];
__device__ float  g_T[2*BATCH*T_LD];
__device__ __half g_feat[(size_t)BATCH*KTOT];   // materialized bilinear features (130MB)
__device__ __half g_w0h[(size_t)H1*KTOT];       // fp16 fc0 weights (130MB)
__device__ __half g_w1h[H2*H1];
__device__ float  g_part0[(size_t)S0*BATCH*H1]; // 128MB
__device__ __half g_h0h[BATCH*H1];
__device__ float  g_part1[(size_t)S1*BATCH*H2]; // 16MB
__device__ float  g_h1[BATCH*H2];
__device__ int    g_pi[NPAIR];
__device__ int    g_pj[NPAIR];

DI uint32_t smem_u32(const void* p) {
    uint32_t a;
    asm("{ .reg .u64 t; cvta.to.shared.u64 t, %1; cvt.u32.u64 %0, t; }" : "=r"(a) : "l"(p));
    return a;
}

DI void cp_async16(uint32_t dst, const void* src) {
    asm volatile("cp.async.cg.shared.global [%0], [%1], 16;" :: "r"(dst), "l"(src));
}
#define CP_COMMIT() asm volatile("cp.async.commit_group;" ::: "memory")
#define CP_WAIT1()  asm volatile("cp.async.wait_group 1;" ::: "memory")

DI void mma_f16(float* d, const uint32_t* a, const uint32_t* b) {
    asm volatile(
        "mma.sync.aligned.m16n8k16.row.col.f32.f16.f16.f32 "
        "{%0,%1,%2,%3}, {%4,%5,%6,%7}, {%8,%9}, {%0,%1,%2,%3};"
        : "+f"(d[0]), "+f"(d[1]), "+f"(d[2]), "+f"(d[3])
        : "r"(a[0]), "r"(a[1]), "r"(a[2]), "r"(a[3]), "r"(b[0]), "r"(b[1]));
}

DI uint32_t pack_h2(float a, float b) {
    __half2 h = __floats2half2_rn(a, b);
    return *(uint32_t*)&h;
}

// ---------------- SE block (+pair-table init in the extra block) ----------------
__global__ void __launch_bounds__(256) se_kernel(const float* __restrict__ x,
                                                 const float* __restrict__ w1,
                                                 const float* __restrict__ w2) {
    if (blockIdx.x == BATCH) {
        if (threadIdx.x == 0) {
            int idx = 0;
            for (int i = 0; i < NF - 1; i++)
                for (int j = i + 1; j < NF; j++) { g_pi[idx] = i; g_pj[idx] = j; idx++; }
        }
        return;
    }
    __shared__ float xs[X_LD];
    __shared__ float Zs[NF], A1s[4], A2s[NF];
    int b = blockIdx.x, tid = threadIdx.x;
    const float4* xr = (const float4*)(x + (size_t)b * X_LD);
    float4* xs4 = (float4*)xs;
    xs4[tid] = xr[tid];
    xs4[tid + 256] = xr[tid + 256];
    __syncthreads();
    int wid = tid >> 5, lane = tid & 31;
    #pragma unroll
    for (int ff = 0; ff < 4; ff++) {
        int f = wid * 4 + ff;
        float v = xs[f * 64 + lane] + xs[f * 64 + 32 + lane];
        #pragma unroll
        for (int o = 16; o; o >>= 1) v += __shfl_xor_sync(0xffffffffu, v, o);
        if (lane == 0) Zs[f] = v * (1.0f / 64.0f);
    }
    __syncthreads();
    if (tid < 4) {
        float a = 0.f;
        #pragma unroll
        for (int f = 0; f < NF; f++) a += Zs[f] * w1[tid * NF + f];
        A1s[tid] = fmaxf(a, 0.0f);
    }
    __syncthreads();
    if (tid < NF) {
        float a = 0.f;
        #pragma unroll
        for (int r = 0; r < 4; r++) a += A1s[r] * w2[tid * 4 + r];
        A2s[tid] = 1.0f / (1.0f + expf(-a));
    }
    __syncthreads();
    float4* o4 = (float4*)(g_x2 + (size_t)b * X_LD);
    #pragma unroll
    for (int q = 0; q < 2; q++) {
        int i = tid + q * 256;
        float4 v = xs4[i];
        float sc = A2s[i >> 4];
        v.x *= sc; v.y *= sc; v.z *= sc; v.w *= sc;
        o4[i] = v;
    }
}

// t[v][b][i*64+o] = sum_e feats_v[b,i,e] * W_v[i,o,e]
__global__ void __launch_bounds__(256) tfield_kernel(const float* __restrict__ x,
                                                     const float* __restrict__ W1,
                                                     const float* __restrict__ W2) {
    __shared__ float Ws[64 * 68];
    __shared__ float xs[16 * 68];
    __shared__ float ts[1024];
    int v = blockIdx.z, fi = blockIdx.x, b0 = blockIdx.y * 16;
    int tid = threadIdx.x;
    const float* W = (v ? W2 : W1) + (size_t)fi * 4096;
    for (int idx = tid; idx < 4096; idx += 256)
        Ws[(idx >> 6) * 68 + (idx & 63)] = W[idx];
    const float* xsrc = (v ? g_x2 : x) + (size_t)b0 * X_LD + fi * 64;
    for (int idx = tid; idx < 1024; idx += 256)
        xs[(idx >> 6) * 68 + (idx & 63)] = xsrc[(size_t)(idx >> 6) * X_LD + (idx & 63)];
    __syncthreads();
    int o = tid >> 2, bg = tid & 3;
    float s0 = 0.f, s1 = 0.f, s2 = 0.f, s3 = 0.f;
    const float4* wrow = (const float4*)(Ws + o * 68);
    #pragma unroll
    for (int e4 = 0; e4 < 16; e4++) {
        float4 wv = wrow[e4];
        float4 a0 = *(const float4*)(xs + (bg * 4 + 0) * 68 + e4 * 4);
        float4 a1 = *(const float4*)(xs + (bg * 4 + 1) * 68 + e4 * 4);
        float4 a2 = *(const float4*)(xs + (bg * 4 + 2) * 68 + e4 * 4);
        float4 a3 = *(const float4*)(xs + (bg * 4 + 3) * 68 + e4 * 4);
        s0 += wv.x*a0.x + wv.y*a0.y + wv.z*a0.z + wv.w*a0.w;
        s1 += wv.x*a1.x + wv.y*a1.y + wv.z*a1.z + wv.w*a1.w;
        s2 += wv.x*a2.x + wv.y*a2.y + wv.z*a2.z + wv.w*a2.w;
        s3 += wv.x*a3.x + wv.y*a3.y + wv.z*a3.z + wv.w*a3.w;
    }
    ts[(bg * 4 + 0) * 64 + o] = s0;
    ts[(bg * 4 + 1) * 64 + o] = s1;
    ts[(bg * 4 + 2) * 64 + o] = s2;
    ts[(bg * 4 + 3) * 64 + o] = s3;
    __syncthreads();
    float* trow = g_T + (size_t)v * (BATCH * T_LD);
    for (int idx = tid; idx < 1024; idx += 256)
        trow[(size_t)(b0 + (idx >> 6)) * T_LD + fi * 64 + (idx & 63)] = ts[idx];
}

// ---------------- fused prep: featgen + fc0 weight f2h + fc1 weight f2h ----------------
#define PREP_FEAT   31744
#define PREP_W0     63488
#define PREP_W1B    512
__global__ void __launch_bounds__(256) prep_kernel(const float* __restrict__ x,
                                                   const float* __restrict__ fc0w,
                                                   const float* __restrict__ fc1w) {
    int blk = blockIdx.x;
    int tid = threadIdx.x;
    if (blk < PREP_FEAT) {
        int p = blk % NPAIR;
        int rest = blk / NPAIR;        // 0..63
        int b0 = (rest & 31) * 32;
        int v = rest >> 5;
        int r = tid >> 3, ec = (tid & 7) * 8;
        int ip = g_pi[p], jp = g_pj[p];
        int b = b0 + r;
        const float* tb = g_T + (size_t)v * (BATCH * T_LD) + (size_t)b * T_LD + ip * 64 + ec;
        const float* xb = (v ? g_x2 : x) + (size_t)b * X_LD + jp * 64 + ec;
        float4 t0 = *(const float4*)tb, t1 = *(const float4*)(tb + 4);
        float4 x0 = *(const float4*)xb, x1 = *(const float4*)(xb + 4);
        uint4 o;
        o.x = pack_h2(t0.x * x0.x, t0.y * x0.y);
        o.y = pack_h2(t0.z * x0.z, t0.w * x0.w);
        o.z = pack_h2(t1.x * x1.x, t1.y * x1.y);
        o.w = pack_h2(t1.z * x1.z, t1.w * x1.w);
        *(uint4*)(g_feat + (size_t)b * KTOT + v * HALFK + p * 64 + ec) = o;
    } else if (blk < PREP_FEAT + PREP_W0) {
        int i = (blk - PREP_FEAT) * 256 + tid;
        float4 v = ((const float4*)fc0w)[i];
        uint2 o;
        o.x = pack_h2(v.x, v.y);
        o.y = pack_h2(v.z, v.w);
        ((uint2*)g_w0h)[i] = o;
    } else {
        int i = (blk - PREP_FEAT - PREP_W0) * 256 + tid;
        float4 v = ((const float4*)fc1w)[i];
        uint2 o;
        o.x = pack_h2(v.x, v.y);
        o.y = pack_h2(v.z, v.w);
        ((uint2*)g_w1h)[i] = o;
    }
}

// ---------------- mma.sync fp16 GEMM (BK=64, 3-stage cp.async) ----------------
// C[m,n] = sum_k A[m,k] * W[n,k]; A, W fp16 row-major with row stride Ktot.
// CTA decode: mb fastest, then nb, then s -> one s-group's CTAs co-resident in L2.
__global__ void __launch_bounds__(256, 2) gemm_kernel(const __half* __restrict__ Ah,
                                                      const __half* __restrict__ Bw,
                                                      float* __restrict__ Cpart,
                                                      int Ntot, int Ktot, int S) {
    extern __shared__ char smc[];
    uint32_t smb = smem_u32(smc);
    int tid = threadIdx.x;
    int w = tid >> 5, l = tid & 31;
    int wr = w >> 2, wc = w & 3;
    int nbn = Ntot >> 7;
    int mb = blockIdx.x % 8;
    int nb = (blockIdx.x / 8) % nbn;
    int s  = blockIdx.x / (8 * nbn);
    int m0 = mb * 128, n0 = nb * 128;
    int Kper = Ktot / S;
    int k_base = s * Kper;
    int ntiles = Kper >> 6;

    int cr = tid >> 2, cq = tid & 3;   // cp.async: rows cr, cr+64; 16B chunks cq, cq+4

    float acc[4][4][4];
    #pragma unroll
    for (int i = 0; i < 4; i++)
        #pragma unroll
        for (int j = 0; j < 4; j++)
            #pragma unroll
            for (int q = 0; q < 4; q++) acc[i][j][q] = 0.f;

    auto cp_tile = [&](int kg, int st) {
        uint32_t baseA = smb + st * 2 * TBUFH_BYTES;
        uint32_t baseB = baseA + TBUFH_BYTES;
        #pragma unroll
        for (int it = 0; it < 2; it++) {
            int r = cr + it * 64;
            const __half* arow = Ah + (size_t)(m0 + r) * Ktot + kg;
            const __half* brow = Bw + (size_t)(n0 + r) * Ktot + kg;
            uint32_t dA = baseA + r * SROWB;
            uint32_t dB = baseB + r * SROWB;
            #pragma unroll
            for (int c = 0; c < 2; c++) {
                int ch = cq + c * 4;
                cp_async16(dA + ch * 16, arow + ch * 8);
                cp_async16(dB + ch * 16, brow + ch * 8);
            }
        }
    };

    // prologue: stage tiles 0 and 1 as two separate groups
    cp_tile(k_base, 0);
    CP_COMMIT();
    if (ntiles > 1) cp_tile(k_base + 64, 1);
    CP_COMMIT();

    int mlane = l >> 2, klane = l & 3;
    for (int kt = 0; kt < ntiles; kt++) {
        int st = kt % NSTAGE;
        CP_WAIT1();          // tile kt landed; kt+1 may still be in flight
        __syncthreads();
        if (kt + 2 < ntiles)
            cp_tile(k_base + ((kt + 2) << 6), (kt + 2) % NSTAGE);
        CP_COMMIT();         // one group per iteration keeps accounting uniform

        const uint32_t* uA = (const uint32_t*)(smc + st * 2 * TBUFH_BYTES);
        const uint32_t* uB = (const uint32_t*)(smc + st * 2 * TBUFH_BYTES + TBUFH_BYTES);
        #pragma unroll
        for (int ks = 0; ks < 4; ks++) {
            int kw = ks * 8 + klane;
            uint32_t afr[4][4], bfr[4][2];
            #pragma unroll
            for (int mf = 0; mf < 4; mf++) {
                int m = wr * 64 + mf * 16 + mlane;
                afr[mf][0] = uA[m * 36 + kw];
                afr[mf][1] = uA[(m + 8) * 36 + kw];
                afr[mf][2] = uA[m * 36 + kw + 4];
                afr[mf][3] = uA[(m + 8) * 36 + kw + 4];
            }
            #pragma unroll
            for (int nf = 0; nf < 4; nf++) {
                int n = wc * 32 + nf * 8 + mlane;
                bfr[nf][0] = uB[n * 36 + kw];
                bfr[nf][1] = uB[n * 36 + kw + 4];
            }
            #pragma unroll
            for (int mf = 0; mf < 4; mf++)
                #pragma unroll
                for (int nf = 0; nf < 4; nf++)
                    mma_f16(acc[mf][nf], afr[mf], bfr[nf]);
        }
    }

    float* crow = Cpart + ((size_t)s * BATCH + m0 + wr * 64) * Ntot + n0 + wc * 32;
    #pragma unroll
    for (int mf = 0; mf < 4; mf++) {
        int mm = mf * 16 + (l >> 2);
        #pragma unroll
        for (int nf = 0; nf < 4; nf++) {
            int nn = nf * 8 + (l & 3) * 2;
            *(float2*)(crow + (size_t)mm * Ntot + nn) = make_float2(acc[mf][nf][0], acc[mf][nf][1]);
            *(float2*)(crow + (size_t)(mm + 8) * Ntot + nn) = make_float2(acc[mf][nf][2], acc[mf][nf][3]);
        }
    }
}

// ---------------- reductions / final ----------------
__global__ void __launch_bounds__(256) reduce0_kernel(const float* __restrict__ bias) {
    int f = blockIdx.x * 256 + threadIdx.x;   // float4 index, 262144 total
    const float4* p = (const float4*)g_part0;
    float4 b = ((const float4*)bias)[f & 255];
    float sx = b.x, sy = b.y, sz = b.z, sw = b.w;
    #pragma unroll
    for (int i = 0; i < S0; i++) {
        float4 a = p[f + (size_t)i * 262144];
        sx += a.x; sy += a.y; sz += a.z; sw += a.w;
    }
    uint2 o;
    o.x = pack_h2(fmaxf(sx, 0.f), fmaxf(sy, 0.f));
    o.y = pack_h2(fmaxf(sz, 0.f), fmaxf(sw, 0.f));
    ((uint2*)g_h0h)[f] = o;
}

__global__ void __launch_bounds__(256) reduce1_kernel(const float* __restrict__ bias) {
    int f = blockIdx.x * 256 + threadIdx.x;   // float4 index, 131072 total
    const float4* p = (const float4*)g_part1;
    float4 b = ((const float4*)bias)[f & 127];
    float sx = b.x, sy = b.y, sz = b.z, sw = b.w;
    #pragma unroll
    for (int i = 0; i < S1; i++) {
        float4 a = p[f + (size_t)i * 131072];
        sx += a.x; sy += a.y; sz += a.z; sw += a.w;
    }
    float4 o;
    o.x = fmaxf(sx, 0.f); o.y = fmaxf(sy, 0.f);
    o.z = fmaxf(sz, 0.f); o.w = fmaxf(sw, 0.f);
    ((float4*)g_h1)[f] = o;
}

__global__ void __launch_bounds__(256) fc2_kernel(const float* __restrict__ w,
                                                  const float* __restrict__ bias,
                                                  float* __restrict__ out) {
    int wid = threadIdx.x >> 5, lane = threadIdx.x & 31;
    int row = blockIdx.x * 8 + wid;
    const float4* h = (const float4*)(g_h1 + (size_t)row * H2);
    const float4* wv = (const float4*)w;
    float s = 0.f;
    #pragma unroll
    for (int q = 0; q < 4; q++) {
        float4 a = h[lane + q * 32], b = wv[lane + q * 32];
        s += a.x * b.x + a.y * b.y + a.z * b.z + a.w * b.w;
    }
    #pragma unroll
    for (int o = 16; o; o >>= 1) s += __shfl_xor_sync(0xffffffffu, s, o);
    if (lane == 0) out[row] = 1.0f / (1.0f + expf(-(s + bias[0])));
}

// ---------------- launch ----------------
extern "C" void kernel_launch(void* const* d_in, const int* in_sizes, int n_in,
                              void* d_out, int out_size) {
    const float* x    = (const float*)d_in[0];
    const float* W1   = (const float*)d_in[1];
    const float* W2   = (const float*)d_in[2];
    const float* sw1  = (const float*)d_in[3];
    const float* sw2  = (const float*)d_in[4];
    const float* fc0w = (const float*)d_in[5];
    const float* fc0b = (const float*)d_in[6];
    const float* fc1w = (const float*)d_in[7];
    const float* fc1b = (const float*)d_in[8];
    const float* fc2w = (const float*)d_in[9];
    const float* fc2b = (const float*)d_in[10];
    float* out = (float*)d_out;

    __half* w0h;  cudaGetSymbolAddress((void**)&w0h, g_w0h);
    __half* w1h;  cudaGetSymbolAddress((void**)&w1h, g_w1h);
    __half* feat; cudaGetSymbolAddress((void**)&feat, g_feat);
    __half* h0h;  cudaGetSymbolAddress((void**)&h0h, g_h0h);
    float* part0; cudaGetSymbolAddress((void**)&part0, g_part0);
    float* part1; cudaGetSymbolAddress((void**)&part1, g_part1);

    cudaFuncSetAttribute(gemm_kernel, cudaFuncAttributeMaxDynamicSharedMemorySize, SMEM_DYN);

    se_kernel<<<BATCH + 1, 256>>>(x, sw1, sw2);                      // #1 (+pair init)
    tfield_kernel<<<dim3(31, BATCH / 16, 2), 256>>>(x, W1, W2);      // #2
    prep_kernel<<<PREP_FEAT + PREP_W0 + PREP_W1B, 256>>>(x, fc0w, fc1w); // #3
    gemm_kernel<<<8 * 8 * S0, 256, SMEM_DYN>>>(feat, w0h, part0, H1, KTOT, S0); // #4 <- profiled
    reduce0_kernel<<<1024, 256>>>(fc0b);
    gemm_kernel<<<8 * 4 * S1, 256, SMEM_DYN>>>(h0h, w1h, part1, H2, H1, S1);
    reduce1_kernel<<<512, 256>>>(fc1b);
    fc2_kernel<<<BATCH / 8, 256>>>(fc2w, fc2b, out);
}

// round 15
// speedup vs baseline: 1.4673x; 1.0564x over previous
#include <cuda_runtime.h>
#include <cuda_fp16.h>
#include <cstdint>
#include <cstddef>

#define DI __device__ __forceinline__

#define BATCH 1024
#define NF    32
#define NPAIR 496
#define T_LD  1984
#define X_LD  2048
#define HALFK 31744
#define KTOT  63488
#define H1    1024
#define H2    512
#define S0    16                 // fc0 split-K
#define S1    8                  // fc1 split-K

// GEMM tile: BM=128, BN=128, BK=64, 256 threads (8 warps: 2 warp-rows x 4 warp-cols,
// warp tile 64x32). fp16 operands in smem, row stride 72 halves (144B) -> conflict-free
// scalar LDS feed (bank = 4*mlane + klane mod 32, all distinct). 2-stage cp.async pipeline.
#define SROWH 72
#define SROWB 144
#define TBUFH_BYTES (128*SROWB)  // 18432
#define SMEM_DYN (4*TBUFH_BYTES) // 73728

__device__ float  g_x2[BATCH*X_LD];
__device__ __half g_Th[2*BATCH*T_LD];           // bilinear-transformed fields, fp16 (8MB)
__device__ __half g_feat[(size_t)BATCH*KTOT];   // materialized bilinear features (130MB)
__device__ __half g_w0h[(size_t)H1*KTOT];       // fp16 fc0 weights (130MB)
__device__ __half g_w1h[H2*H1];
__device__ float  g_part0[(size_t)S0*BATCH*H1]; // 64MB
__device__ __half g_h0h[BATCH*H1];
__device__ float  g_part1[(size_t)S1*BATCH*H2]; // 16MB
__device__ float  g_h1[BATCH*H2];
__device__ int    g_pi[NPAIR];
__device__ int    g_pj[NPAIR];

DI uint32_t smem_u32(const void* p) {
    uint32_t a;
    asm("{ .reg .u64 t; cvta.to.shared.u64 t, %1; cvt.u32.u64 %0, t; }" : "=r"(a) : "l"(p));
    return a;
}

DI void cp_async16(uint32_t dst, const void* src) {
    asm volatile("cp.async.cg.shared.global [%0], [%1], 16;" :: "r"(dst), "l"(src));
}
#define CP_COMMIT() asm volatile("cp.async.commit_group;" ::: "memory")
#define CP_WAIT0()  asm volatile("cp.async.wait_group 0;" ::: "memory")

DI void mma_f16(float* d, const uint32_t* a, const uint32_t* b) {
    asm volatile(
        "mma.sync.aligned.m16n8k16.row.col.f32.f16.f16.f32 "
        "{%0,%1,%2,%3}, {%4,%5,%6,%7}, {%8,%9}, {%0,%1,%2,%3};"
        : "+f"(d[0]), "+f"(d[1]), "+f"(d[2]), "+f"(d[3])
        : "r"(a[0]), "r"(a[1]), "r"(a[2]), "r"(a[3]), "r"(b[0]), "r"(b[1]));
}

DI uint32_t pack_h2(float a, float b) {
    __half2 h = __floats2half2_rn(a, b);
    return *(uint32_t*)&h;
}

// ---------------- SE block (+pair-table init in the extra block) ----------------
__global__ void __launch_bounds__(256) se_kernel(const float* __restrict__ x,
                                                 const float* __restrict__ w1,
                                                 const float* __restrict__ w2) {
    if (blockIdx.x == BATCH) {
        if (threadIdx.x == 0) {
            int idx = 0;
            for (int i = 0; i < NF - 1; i++)
                for (int j = i + 1; j < NF; j++) { g_pi[idx] = i; g_pj[idx] = j; idx++; }
        }
        return;
    }
    __shared__ float xs[X_LD];
    __shared__ float Zs[NF], A1s[4], A2s[NF];
    int b = blockIdx.x, tid = threadIdx.x;
    const float4* xr = (const float4*)(x + (size_t)b * X_LD);
    float4* xs4 = (float4*)xs;
    xs4[tid] = xr[tid];
    xs4[tid + 256] = xr[tid + 256];
    __syncthreads();
    int wid = tid >> 5, lane = tid & 31;
    #pragma unroll
    for (int ff = 0; ff < 4; ff++) {
        int f = wid * 4 + ff;
        float v = xs[f * 64 + lane] + xs[f * 64 + 32 + lane];
        #pragma unroll
        for (int o = 16; o; o >>= 1) v += __shfl_xor_sync(0xffffffffu, v, o);
        if (lane == 0) Zs[f] = v * (1.0f / 64.0f);
    }
    __syncthreads();
    if (tid < 4) {
        float a = 0.f;
        #pragma unroll
        for (int f = 0; f < NF; f++) a += Zs[f] * w1[tid * NF + f];
        A1s[tid] = fmaxf(a, 0.0f);
    }
    __syncthreads();
    if (tid < NF) {
        float a = 0.f;
        #pragma unroll
        for (int r = 0; r < 4; r++) a += A1s[r] * w2[tid * 4 + r];
        A2s[tid] = 1.0f / (1.0f + expf(-a));
    }
    __syncthreads();
    float4* o4 = (float4*)(g_x2 + (size_t)b * X_LD);
    #pragma unroll
    for (int q = 0; q < 2; q++) {
        int i = tid + q * 256;
        float4 v = xs4[i];
        float sc = A2s[i >> 4];
        v.x *= sc; v.y *= sc; v.z *= sc; v.w *= sc;
        o4[i] = v;
    }
}

// t[v][b][i*64+o] = sum_e feats_v[b,i,e] * W_v[i,o,e]  (output fp16)
__global__ void __launch_bounds__(256) tfield_kernel(const float* __restrict__ x,
                                                     const float* __restrict__ W1,
                                                     const float* __restrict__ W2) {
    __shared__ float Ws[64 * 68];
    __shared__ float xs[16 * 68];
    __shared__ float ts[1024];
    int v = blockIdx.z, fi = blockIdx.x, b0 = blockIdx.y * 16;
    int tid = threadIdx.x;
    const float* W = (v ? W2 : W1) + (size_t)fi * 4096;
    for (int idx = tid; idx < 4096; idx += 256)
        Ws[(idx >> 6) * 68 + (idx & 63)] = W[idx];
    const float* xsrc = (v ? g_x2 : x) + (size_t)b0 * X_LD + fi * 64;
    for (int idx = tid; idx < 1024; idx += 256)
        xs[(idx >> 6) * 68 + (idx & 63)] = xsrc[(size_t)(idx >> 6) * X_LD + (idx & 63)];
    __syncthreads();
    int o = tid >> 2, bg = tid & 3;
    float s0 = 0.f, s1 = 0.f, s2 = 0.f, s3 = 0.f;
    const float4* wrow = (const float4*)(Ws + o * 68);
    #pragma unroll
    for (int e4 = 0; e4 < 16; e4++) {
        float4 wv = wrow[e4];
        float4 a0 = *(const float4*)(xs + (bg * 4 + 0) * 68 + e4 * 4);
        float4 a1 = *(const float4*)(xs + (bg * 4 + 1) * 68 + e4 * 4);
        float4 a2 = *(const float4*)(xs + (bg * 4 + 2) * 68 + e4 * 4);
        float4 a3 = *(const float4*)(xs + (bg * 4 + 3) * 68 + e4 * 4);
        s0 += wv.x*a0.x + wv.y*a0.y + wv.z*a0.z + wv.w*a0.w;
        s1 += wv.x*a1.x + wv.y*a1.y + wv.z*a1.z + wv.w*a1.w;
        s2 += wv.x*a2.x + wv.y*a2.y + wv.z*a2.z + wv.w*a2.w;
        s3 += wv.x*a3.x + wv.y*a3.y + wv.z*a3.z + wv.w*a3.w;
    }
    ts[(bg * 4 + 0) * 64 + o] = s0;
    ts[(bg * 4 + 1) * 64 + o] = s1;
    ts[(bg * 4 + 2) * 64 + o] = s2;
    ts[(bg * 4 + 3) * 64 + o] = s3;
    __syncthreads();
    __half* trow = g_Th + (size_t)v * (BATCH * T_LD);
    for (int idx = tid; idx < 512; idx += 256) {
        int r = idx >> 5, c2 = idx & 31;   // row 0..15, 2-float chunk 0..31
        float2 tv = *(const float2*)(ts + r * 64 + c2 * 2);
        uint32_t h = pack_h2(tv.x, tv.y);
        *(uint32_t*)(trow + (size_t)(b0 + r) * T_LD + fi * 64 + c2 * 2) = h;
    }
}

// ---------------- fused prep: featgen + fc0 weight f2h + fc1 weight f2h ----------------
#define PREP_FEAT   31744
#define PREP_W0     63488
#define PREP_W1B    512
__global__ void __launch_bounds__(256) prep_kernel(const float* __restrict__ x,
                                                   const float* __restrict__ fc0w,
                                                   const float* __restrict__ fc1w) {
    int blk = blockIdx.x;
    int tid = threadIdx.x;
    if (blk < PREP_FEAT) {
        int p = blk % NPAIR;
        int rest = blk / NPAIR;        // 0..63
        int b0 = (rest & 31) * 32;
        int v = rest >> 5;
        int r = tid >> 3, ec = (tid & 7) * 8;
        int ip = g_pi[p], jp = g_pj[p];
        int b = b0 + r;
        const __half* tb = g_Th + (size_t)v * (BATCH * T_LD) + (size_t)b * T_LD + ip * 64 + ec;
        const float*  xb = (v ? g_x2 : x) + (size_t)b * X_LD + jp * 64 + ec;
        uint4 th = *(const uint4*)tb;  // 8 halves
        float4 x0 = *(const float4*)xb, x1 = *(const float4*)(xb + 4);
        float2 t0 = __half22float2(*(__half2*)&th.x);
        float2 t1 = __half22float2(*(__half2*)&th.y);
        float2 t2 = __half22float2(*(__half2*)&th.z);
        float2 t3 = __half22float2(*(__half2*)&th.w);
        uint4 o;
        o.x = pack_h2(t0.x * x0.x, t0.y * x0.y);
        o.y = pack_h2(t1.x * x0.z, t1.y * x0.w);
        o.z = pack_h2(t2.x * x1.x, t2.y * x1.y);
        o.w = pack_h2(t3.x * x1.z, t3.y * x1.w);
        *(uint4*)(g_feat + (size_t)b * KTOT + v * HALFK + p * 64 + ec) = o;
    } else if (blk < PREP_FEAT + PREP_W0) {
        int i = (blk - PREP_FEAT) * 256 + tid;
        float4 v = ((const float4*)fc0w)[i];
        uint2 o;
        o.x = pack_h2(v.x, v.y);
        o.y = pack_h2(v.z, v.w);
        ((uint2*)g_w0h)[i] = o;
    } else {
        int i = (blk - PREP_FEAT - PREP_W0) * 256 + tid;
        float4 v = ((const float4*)fc1w)[i];
        uint2 o;
        o.x = pack_h2(v.x, v.y);
        o.y = pack_h2(v.z, v.w);
        ((uint2*)g_w1h)[i] = o;
    }
}

// ---------------- mma.sync fp16 GEMM (BK=64, 2-stage cp.async, interleaved feed) ----------------
// C[m,n] = sum_k A[m,k] * W[n,k]; A, W fp16 row-major with row stride Ktot.
// CTA decode: mb fastest, then nb, then s -> one s-group's CTAs co-resident in L2.
__global__ void __launch_bounds__(256, 2) gemm_kernel(const __half* __restrict__ Ah,
                                                      const __half* __restrict__ Bw,
                                                      float* __restrict__ Cpart,
                                                      int Ntot, int Ktot, int S) {
    extern __shared__ char smc[];
    uint32_t smb = smem_u32(smc);
    int tid = threadIdx.x;
    int w = tid >> 5, l = tid & 31;
    int wr = w >> 2, wc = w & 3;
    int nbn = Ntot >> 7;
    int mb = blockIdx.x % 8;
    int nb = (blockIdx.x / 8) % nbn;
    int s  = blockIdx.x / (8 * nbn);
    int m0 = mb * 128, n0 = nb * 128;
    int Kper = Ktot / S;
    int k_base = s * Kper;
    int ntiles = Kper >> 6;

    int cr = tid >> 2, cq = tid & 3;   // cp.async: rows cr, cr+64; 16B chunks cq, cq+4

    float acc[4][4][4];
    #pragma unroll
    for (int i = 0; i < 4; i++)
        #pragma unroll
        for (int j = 0; j < 4; j++)
            #pragma unroll
            for (int q = 0; q < 4; q++) acc[i][j][q] = 0.f;

    auto cp_tile = [&](int kg, int st) {
        uint32_t baseA = smb + st * 2 * TBUFH_BYTES;
        uint32_t baseB = baseA + TBUFH_BYTES;
        #pragma unroll
        for (int it = 0; it < 2; it++) {
            int r = cr + it * 64;
            const __half* arow = Ah + (size_t)(m0 + r) * Ktot + kg;
            const __half* brow = Bw + (size_t)(n0 + r) * Ktot + kg;
            uint32_t dA = baseA + r * SROWB;
            uint32_t dB = baseB + r * SROWB;
            #pragma unroll
            for (int c = 0; c < 2; c++) {
                int ch = cq + c * 4;
                cp_async16(dA + ch * 16, arow + ch * 8);
                cp_async16(dB + ch * 16, brow + ch * 8);
            }
        }
    };

    cp_tile(k_base, 0);
    CP_COMMIT();

    int mlane = l >> 2, klane = l & 3;
    for (int kt = 0; kt < ntiles; kt++) {
        int st = kt & 1;
        CP_WAIT0();
        __syncthreads();
        if (kt + 1 < ntiles) {
            cp_tile(k_base + ((kt + 1) << 6), st ^ 1);
            CP_COMMIT();
        }

        const uint32_t* uA = (const uint32_t*)(smc + st * 2 * TBUFH_BYTES);
        const uint32_t* uB = (const uint32_t*)(smc + st * 2 * TBUFH_BYTES + TBUFH_BYTES);
        #pragma unroll
        for (int ks = 0; ks < 4; ks++) {
            int kw = ks * 8 + klane;
            uint32_t afr[4][4];
            #pragma unroll
            for (int mf = 0; mf < 4; mf++) {
                int m = wr * 64 + mf * 16 + mlane;
                afr[mf][0] = uA[m * 36 + kw];
                afr[mf][1] = uA[(m + 8) * 36 + kw];
                afr[mf][2] = uA[m * 36 + kw + 4];
                afr[mf][3] = uA[(m + 8) * 36 + kw + 4];
            }
            // Interleave: load each B fragment right before its MMA group.
            #pragma unroll
            for (int nf = 0; nf < 4; nf++) {
                int n = wc * 32 + nf * 8 + mlane;
                uint32_t bfr[2];
                bfr[0] = uB[n * 36 + kw];
                bfr[1] = uB[n * 36 + kw + 4];
                #pragma unroll
                for (int mf = 0; mf < 4; mf++)
                    mma_f16(acc[mf][nf], afr[mf], bfr);
            }
        }
    }

    float* crow = Cpart + ((size_t)s * BATCH + m0 + wr * 64) * Ntot + n0 + wc * 32;
    #pragma unroll
    for (int mf = 0; mf < 4; mf++) {
        int mm = mf * 16 + (l >> 2);
        #pragma unroll
        for (int nf = 0; nf < 4; nf++) {
            int nn = nf * 8 + (l & 3) * 2;
            *(float2*)(crow + (size_t)mm * Ntot + nn) = make_float2(acc[mf][nf][0], acc[mf][nf][1]);
            *(float2*)(crow + (size_t)(mm + 8) * Ntot + nn) = make_float2(acc[mf][nf][2], acc[mf][nf][3]);
        }
    }
}

// ---------------- reductions / final ----------------
__global__ void __launch_bounds__(256) reduce0_kernel(const float* __restrict__ bias) {
    int f = blockIdx.x * 256 + threadIdx.x;   // float4 index, 262144 total
    const float4* p = (const float4*)g_part0;
    float4 b = ((const float4*)bias)[f & 255];
    float sx = b.x, sy = b.y, sz = b.z, sw = b.w;
    #pragma unroll
    for (int i = 0; i < S0; i++) {
        float4 a = p[f + (size_t)i * 262144];
        sx += a.x; sy += a.y; sz += a.z; sw += a.w;
    }
    uint2 o;
    o.x = pack_h2(fmaxf(sx, 0.f), fmaxf(sy, 0.f));
    o.y = pack_h2(fmaxf(sz, 0.f), fmaxf(sw, 0.f));
    ((uint2*)g_h0h)[f] = o;
}

__global__ void __launch_bounds__(256) reduce1_kernel(const float* __restrict__ bias) {
    int f = blockIdx.x * 256 + threadIdx.x;   // float4 index, 131072 total
    const float4* p = (const float4*)g_part1;
    float4 b = ((const float4*)bias)[f & 127];
    float sx = b.x, sy = b.y, sz = b.z, sw = b.w;
    #pragma unroll
    for (int i = 0; i < S1; i++) {
        float4 a = p[f + (size_t)i * 131072];
        sx += a.x; sy += a.y; sz += a.z; sw += a.w;
    }
    float4 o;
    o.x = fmaxf(sx, 0.f); o.y = fmaxf(sy, 0.f);
    o.z = fmaxf(sz, 0.f); o.w = fmaxf(sw, 0.f);
    ((float4*)g_h1)[f] = o;
}

__global__ void __launch_bounds__(256) fc2_kernel(const float* __restrict__ w,
                                                  const float* __restrict__ bias,
                                                  float* __restrict__ out) {
    int wid = threadIdx.x >> 5, lane = threadIdx.x & 31;
    int row = blockIdx.x * 8 + wid;
    const float4* h = (const float4*)(g_h1 + (size_t)row * H2);
    const float4* wv = (const float4*)w;
    float s = 0.f;
    #pragma unroll
    for (int q = 0; q < 4; q++) {
        float4 a = h[lane + q * 32], b = wv[lane + q * 32];
        s += a.x * b.x + a.y * b.y + a.z * b.z + a.w * b.w;
    }
    #pragma unroll
    for (int o = 16; o; o >>= 1) s += __shfl_xor_sync(0xffffffffu, s, o);
    if (lane == 0) out[row] = 1.0f / (1.0f + expf(-(s + bias[0])));
}

// ---------------- launch ----------------
extern "C" void kernel_launch(void* const* d_in, const int* in_sizes, int n_in,
                              void* d_out, int out_size) {
    const float* x    = (const float*)d_in[0];
    const float* W1   = (const float*)d_in[1];
    const float* W2   = (const float*)d_in[2];
    const float* sw1  = (const float*)d_in[3];
    const float* sw2  = (const float*)d_in[4];
    const float* fc0w = (const float*)d_in[5];
    const float* fc0b = (const float*)d_in[6];
    const float* fc1w = (const float*)d_in[7];
    const float* fc1b = (const float*)d_in[8];
    const float* fc2w = (const float*)d_in[9];
    const float* fc2b = (const float*)d_in[10];
    float* out = (float*)d_out;

    __half* w0h;  cudaGetSymbolAddress((void**)&w0h, g_w0h);
    __half* w1h;  cudaGetSymbolAddress((void**)&w1h, g_w1h);
    __half* feat; cudaGetSymbolAddress((void**)&feat, g_feat);
    __half* h0h;  cudaGetSymbolAddress((void**)&h0h, g_h0h);
    float* part0; cudaGetSymbolAddress((void**)&part0, g_part0);
    float* part1; cudaGetSymbolAddress((void**)&part1, g_part1);

    cudaFuncSetAttribute(gemm_kernel, cudaFuncAttributeMaxDynamicSharedMemorySize, SMEM_DYN);

    se_kernel<<<BATCH + 1, 256>>>(x, sw1, sw2);                      // #1 (+pair init)
    tfield_kernel<<<dim3(31, BATCH / 16, 2), 256>>>(x, W1, W2);      // #2
    prep_kernel<<<PREP_FEAT + PREP_W0 + PREP_W1B, 256>>>(x, fc0w, fc1w); // #3
    gemm_kernel<<<8 * 8 * S0, 256, SMEM_DYN>>>(feat, w0h, part0, H1, KTOT, S0); // #4 <- profiled
    reduce0_kernel<<<1024, 256>>>(fc0b);
    gemm_kernel<<<8 * 4 * S1, 256, SMEM_DYN>>>(h0h, w1h, part1, H2, H1, S1);
    reduce1_kernel<<<512, 256>>>(fc1b);
    fc2_kernel<<<BATCH / 8, 256>>>(fc2w, fc2b, out);
}

// round 16
// speedup vs baseline: 1.4878x; 1.0140x over previous
#include <cuda_runtime.h>
#include <cuda_fp16.h>
#include <cstdint>
#include <cstddef>

#define DI __device__ __forceinline__

#define BATCH 1024
#define NF    32
#define NPAIR 496
#define T_LD  1984
#define X_LD  2048
#define HALFK 31744
#define KTOT  63488
#define H1    1024
#define H2    512
#define S0    16                 // fc0 split-K
#define S1    8                  // fc1 split-K

// GEMM tile: BM=128, BN=128, BK=64, 256 threads (8 warps: 2 warp-rows x 4 warp-cols,
// warp tile 64x32). fp16 operands in smem, row stride 72 halves (144B) -> conflict-free
// scalar LDS feed (bank = 4*mlane + klane mod 32, all distinct). 2-stage cp.async pipeline.
#define SROWH 72
#define SROWB 144
#define TBUFH_BYTES (128*SROWB)  // 18432
#define SMEM_DYN (4*TBUFH_BYTES) // 73728

__device__ float  g_x2[BATCH*X_LD];
__device__ __half g_Th[2*BATCH*T_LD];           // bilinear-transformed fields, fp16 (8MB)
__device__ __half g_feat[(size_t)BATCH*KTOT];   // materialized bilinear features (130MB)
__device__ __half g_w0h[(size_t)H1*KTOT];       // fp16 fc0 weights (130MB)
__device__ __half g_w1h[H2*H1];
__device__ float  g_part0[(size_t)S0*BATCH*H1]; // 64MB
__device__ __half g_h0h[BATCH*H1];
__device__ float  g_part1[(size_t)S1*BATCH*H2]; // 16MB
__device__ float  g_h1[BATCH*H2];
__device__ int    g_pi[NPAIR];
__device__ int    g_pj[NPAIR];

DI uint32_t smem_u32(const void* p) {
    uint32_t a;
    asm("{ .reg .u64 t; cvta.to.shared.u64 t, %1; cvt.u32.u64 %0, t; }" : "=r"(a) : "l"(p));
    return a;
}

DI void cp_async16(uint32_t dst, const void* src) {
    asm volatile("cp.async.cg.shared.global [%0], [%1], 16;" :: "r"(dst), "l"(src));
}
#define CP_COMMIT() asm volatile("cp.async.commit_group;" ::: "memory")
#define CP_WAIT0()  asm volatile("cp.async.wait_group 0;" ::: "memory")

DI void mma_f16(float* d, const uint32_t* a, const uint32_t* b) {
    asm volatile(
        "mma.sync.aligned.m16n8k16.row.col.f32.f16.f16.f32 "
        "{%0,%1,%2,%3}, {%4,%5,%6,%7}, {%8,%9}, {%0,%1,%2,%3};"
        : "+f"(d[0]), "+f"(d[1]), "+f"(d[2]), "+f"(d[3])
        : "r"(a[0]), "r"(a[1]), "r"(a[2]), "r"(a[3]), "r"(b[0]), "r"(b[1]));
}

DI uint32_t pack_h2(float a, float b) {
    __half2 h = __floats2half2_rn(a, b);
    return *(uint32_t*)&h;
}

// ---------------- SE block (+pair-table init in the extra block) ----------------
__global__ void __launch_bounds__(256) se_kernel(const float* __restrict__ x,
                                                 const float* __restrict__ w1,
                                                 const float* __restrict__ w2) {
    if (blockIdx.x == BATCH) {
        if (threadIdx.x == 0) {
            int idx = 0;
            for (int i = 0; i < NF - 1; i++)
                for (int j = i + 1; j < NF; j++) { g_pi[idx] = i; g_pj[idx] = j; idx++; }
        }
        return;
    }
    __shared__ float xs[X_LD];
    __shared__ float Zs[NF], A1s[4], A2s[NF];
    int b = blockIdx.x, tid = threadIdx.x;
    const float4* xr = (const float4*)(x + (size_t)b * X_LD);
    float4* xs4 = (float4*)xs;
    xs4[tid] = xr[tid];
    xs4[tid + 256] = xr[tid + 256];
    __syncthreads();
    int wid = tid >> 5, lane = tid & 31;
    #pragma unroll
    for (int ff = 0; ff < 4; ff++) {
        int f = wid * 4 + ff;
        float v = xs[f * 64 + lane] + xs[f * 64 + 32 + lane];
        #pragma unroll
        for (int o = 16; o; o >>= 1) v += __shfl_xor_sync(0xffffffffu, v, o);
        if (lane == 0) Zs[f] = v * (1.0f / 64.0f);
    }
    __syncthreads();
    if (tid < 4) {
        float a = 0.f;
        #pragma unroll
        for (int f = 0; f < NF; f++) a += Zs[f] * w1[tid * NF + f];
        A1s[tid] = fmaxf(a, 0.0f);
    }
    __syncthreads();
    if (tid < NF) {
        float a = 0.f;
        #pragma unroll
        for (int r = 0; r < 4; r++) a += A1s[r] * w2[tid * 4 + r];
        A2s[tid] = 1.0f / (1.0f + expf(-a));
    }
    __syncthreads();
    float4* o4 = (float4*)(g_x2 + (size_t)b * X_LD);
    #pragma unroll
    for (int q = 0; q < 2; q++) {
        int i = tid + q * 256;
        float4 v = xs4[i];
        float sc = A2s[i >> 4];
        v.x *= sc; v.y *= sc; v.z *= sc; v.w *= sc;
        o4[i] = v;
    }
}

// t[v][b][i*64+o] = sum_e feats_v[b,i,e] * W_v[i,o,e]  (output fp16)
__global__ void __launch_bounds__(256) tfield_kernel(const float* __restrict__ x,
                                                     const float* __restrict__ W1,
                                                     const float* __restrict__ W2) {
    __shared__ float Ws[64 * 68];
    __shared__ float xs[16 * 68];
    __shared__ float ts[1024];
    int v = blockIdx.z, fi = blockIdx.x, b0 = blockIdx.y * 16;
    int tid = threadIdx.x;
    const float* W = (v ? W2 : W1) + (size_t)fi * 4096;
    for (int idx = tid; idx < 4096; idx += 256)
        Ws[(idx >> 6) * 68 + (idx & 63)] = W[idx];
    const float* xsrc = (v ? g_x2 : x) + (size_t)b0 * X_LD + fi * 64;
    for (int idx = tid; idx < 1024; idx += 256)
        xs[(idx >> 6) * 68 + (idx & 63)] = xsrc[(size_t)(idx >> 6) * X_LD + (idx & 63)];
    __syncthreads();
    int o = tid >> 2, bg = tid & 3;
    float s0 = 0.f, s1 = 0.f, s2 = 0.f, s3 = 0.f;
    const float4* wrow = (const float4*)(Ws + o * 68);
    #pragma unroll
    for (int e4 = 0; e4 < 16; e4++) {
        float4 wv = wrow[e4];
        float4 a0 = *(const float4*)(xs + (bg * 4 + 0) * 68 + e4 * 4);
        float4 a1 = *(const float4*)(xs + (bg * 4 + 1) * 68 + e4 * 4);
        float4 a2 = *(const float4*)(xs + (bg * 4 + 2) * 68 + e4 * 4);
        float4 a3 = *(const float4*)(xs + (bg * 4 + 3) * 68 + e4 * 4);
        s0 += wv.x*a0.x + wv.y*a0.y + wv.z*a0.z + wv.w*a0.w;
        s1 += wv.x*a1.x + wv.y*a1.y + wv.z*a1.z + wv.w*a1.w;
        s2 += wv.x*a2.x + wv.y*a2.y + wv.z*a2.z + wv.w*a2.w;
        s3 += wv.x*a3.x + wv.y*a3.y + wv.z*a3.z + wv.w*a3.w;
    }
    ts[(bg * 4 + 0) * 64 + o] = s0;
    ts[(bg * 4 + 1) * 64 + o] = s1;
    ts[(bg * 4 + 2) * 64 + o] = s2;
    ts[(bg * 4 + 3) * 64 + o] = s3;
    __syncthreads();
    __half* trow = g_Th + (size_t)v * (BATCH * T_LD);
    for (int idx = tid; idx < 512; idx += 256) {
        int r = idx >> 5, c2 = idx & 31;   // row 0..15, 2-float chunk 0..31
        float2 tv = *(const float2*)(ts + r * 64 + c2 * 2);
        uint32_t h = pack_h2(tv.x, tv.y);
        *(uint32_t*)(trow + (size_t)(b0 + r) * T_LD + fi * 64 + c2 * 2) = h;
    }
}

// ---------------- fused prep: featgen + fc0 weight f2h + fc1 weight f2h ----------------
// featgen blocks: [0, 31744)
// W0 f2h blocks:  [31744, 47616)  — 15872 blocks x 1024 float4s (4 per thread, MLP=4)
// W1 f2h blocks:  [47616, 47744)  — 128 blocks x 1024 float4s
#define PREP_FEAT   31744
#define PREP_W0B    15872
#define PREP_W1B    128
__global__ void __launch_bounds__(256) prep_kernel(const float* __restrict__ x,
                                                   const float* __restrict__ fc0w,
                                                   const float* __restrict__ fc1w) {
    int blk = blockIdx.x;
    int tid = threadIdx.x;
    if (blk < PREP_FEAT) {
        int p = blk % NPAIR;
        int rest = blk / NPAIR;        // 0..63
        int b0 = (rest & 31) * 32;
        int v = rest >> 5;
        int r = tid >> 3, ec = (tid & 7) * 8;
        int ip = g_pi[p], jp = g_pj[p];
        int b = b0 + r;
        const __half* tb = g_Th + (size_t)v * (BATCH * T_LD) + (size_t)b * T_LD + ip * 64 + ec;
        const float*  xb = (v ? g_x2 : x) + (size_t)b * X_LD + jp * 64 + ec;
        uint4 th = *(const uint4*)tb;  // 8 halves
        float4 x0 = *(const float4*)xb, x1 = *(const float4*)(xb + 4);
        float2 t0 = __half22float2(*(__half2*)&th.x);
        float2 t1 = __half22float2(*(__half2*)&th.y);
        float2 t2 = __half22float2(*(__half2*)&th.z);
        float2 t3 = __half22float2(*(__half2*)&th.w);
        uint4 o;
        o.x = pack_h2(t0.x * x0.x, t0.y * x0.y);
        o.y = pack_h2(t1.x * x0.z, t1.y * x0.w);
        o.z = pack_h2(t2.x * x1.x, t2.y * x1.y);
        o.w = pack_h2(t3.x * x1.z, t3.y * x1.w);
        *(uint4*)(g_feat + (size_t)b * KTOT + v * HALFK + p * 64 + ec) = o;
    } else if (blk < PREP_FEAT + PREP_W0B) {
        // 4 independent float4 loads per thread -> MLP=4
        size_t base = (size_t)(blk - PREP_FEAT) * 1024 + tid;
        float4 v0 = ((const float4*)fc0w)[base];
        float4 v1 = ((const float4*)fc0w)[base + 256];
        float4 v2 = ((const float4*)fc0w)[base + 512];
        float4 v3 = ((const float4*)fc0w)[base + 768];
        uint2 o0, o1, o2, o3;
        o0.x = pack_h2(v0.x, v0.y); o0.y = pack_h2(v0.z, v0.w);
        o1.x = pack_h2(v1.x, v1.y); o1.y = pack_h2(v1.z, v1.w);
        o2.x = pack_h2(v2.x, v2.y); o2.y = pack_h2(v2.z, v2.w);
        o3.x = pack_h2(v3.x, v3.y); o3.y = pack_h2(v3.z, v3.w);
        ((uint2*)g_w0h)[base] = o0;
        ((uint2*)g_w0h)[base + 256] = o1;
        ((uint2*)g_w0h)[base + 512] = o2;
        ((uint2*)g_w0h)[base + 768] = o3;
    } else {
        size_t base = (size_t)(blk - PREP_FEAT - PREP_W0B) * 1024 + tid;
        float4 v0 = ((const float4*)fc1w)[base];
        float4 v1 = ((const float4*)fc1w)[base + 256];
        float4 v2 = ((const float4*)fc1w)[base + 512];
        float4 v3 = ((const float4*)fc1w)[base + 768];
        uint2 o0, o1, o2, o3;
        o0.x = pack_h2(v0.x, v0.y); o0.y = pack_h2(v0.z, v0.w);
        o1.x = pack_h2(v1.x, v1.y); o1.y = pack_h2(v1.z, v1.w);
        o2.x = pack_h2(v2.x, v2.y); o2.y = pack_h2(v2.z, v2.w);
        o3.x = pack_h2(v3.x, v3.y); o3.y = pack_h2(v3.z, v3.w);
        ((uint2*)g_w1h)[base] = o0;
        ((uint2*)g_w1h)[base + 256] = o1;
        ((uint2*)g_w1h)[base + 512] = o2;
        ((uint2*)g_w1h)[base + 768] = o3;
    }
}

// ---------------- mma.sync fp16 GEMM (BK=64, 2-stage cp.async, interleaved feed) ----------------
// C[m,n] = sum_k A[m,k] * W[n,k]; A, W fp16 row-major with row stride Ktot.
// CTA decode: mb fastest, then nb, then s -> one s-group's CTAs co-resident in L2.
__global__ void __launch_bounds__(256, 2) gemm_kernel(const __half* __restrict__ Ah,
                                                      const __half* __restrict__ Bw,
                                                      float* __restrict__ Cpart,
                                                      int Ntot, int Ktot, int S) {
    extern __shared__ char smc[];
    uint32_t smb = smem_u32(smc);
    int tid = threadIdx.x;
    int w = tid >> 5, l = tid & 31;
    int wr = w >> 2, wc = w & 3;
    int nbn = Ntot >> 7;
    int mb = blockIdx.x % 8;
    int nb = (blockIdx.x / 8) % nbn;
    int s  = blockIdx.x / (8 * nbn);
    int m0 = mb * 128, n0 = nb * 128;
    int Kper = Ktot / S;
    int k_base = s * Kper;
    int ntiles = Kper >> 6;

    int cr = tid >> 2, cq = tid & 3;   // cp.async: rows cr, cr+64; 16B chunks cq, cq+4

    float acc[4][4][4];
    #pragma unroll
    for (int i = 0; i < 4; i++)
        #pragma unroll
        for (int j = 0; j < 4; j++)
            #pragma unroll
            for (int q = 0; q < 4; q++) acc[i][j][q] = 0.f;

    auto cp_tile = [&](int kg, int st) {
        uint32_t baseA = smb + st * 2 * TBUFH_BYTES;
        uint32_t baseB = baseA + TBUFH_BYTES;
        #pragma unroll
        for (int it = 0; it < 2; it++) {
            int r = cr + it * 64;
            const __half* arow = Ah + (size_t)(m0 + r) * Ktot + kg;
            const __half* brow = Bw + (size_t)(n0 + r) * Ktot + kg;
            uint32_t dA = baseA + r * SROWB;
            uint32_t dB = baseB + r * SROWB;
            #pragma unroll
            for (int c = 0; c < 2; c++) {
                int ch = cq + c * 4;
                cp_async16(dA + ch * 16, arow + ch * 8);
                cp_async16(dB + ch * 16, brow + ch * 8);
            }
        }
    };

    cp_tile(k_base, 0);
    CP_COMMIT();

    int mlane = l >> 2, klane = l & 3;
    for (int kt = 0; kt < ntiles; kt++) {
        int st = kt & 1;
        CP_WAIT0();
        __syncthreads();
        if (kt + 1 < ntiles) {
            cp_tile(k_base + ((kt + 1) << 6), st ^ 1);
            CP_COMMIT();
        }

        const uint32_t* uA = (const uint32_t*)(smc + st * 2 * TBUFH_BYTES);
        const uint32_t* uB = (const uint32_t*)(smc + st * 2 * TBUFH_BYTES + TBUFH_BYTES);
        #pragma unroll
        for (int ks = 0; ks < 4; ks++) {
            int kw = ks * 8 + klane;
            uint32_t afr[4][4];
            #pragma unroll
            for (int mf = 0; mf < 4; mf++) {
                int m = wr * 64 + mf * 16 + mlane;
                afr[mf][0] = uA[m * 36 + kw];
                afr[mf][1] = uA[(m + 8) * 36 + kw];
                afr[mf][2] = uA[m * 36 + kw + 4];
                afr[mf][3] = uA[(m + 8) * 36 + kw + 4];
            }
            // Interleave: load each B fragment right before its MMA group.
            #pragma unroll
            for (int nf = 0; nf < 4; nf++) {
                int n = wc * 32 + nf * 8 + mlane;
                uint32_t bfr[2];
                bfr[0] = uB[n * 36 + kw];
                bfr[1] = uB[n * 36 + kw + 4];
                #pragma unroll
                for (int mf = 0; mf < 4; mf++)
                    mma_f16(acc[mf][nf], afr[mf], bfr);
            }
        }
    }

    float* crow = Cpart + ((size_t)s * BATCH + m0 + wr * 64) * Ntot + n0 + wc * 32;
    #pragma unroll
    for (int mf = 0; mf < 4; mf++) {
        int mm = mf * 16 + (l >> 2);
        #pragma unroll
        for (int nf = 0; nf < 4; nf++) {
            int nn = nf * 8 + (l & 3) * 2;
            *(float2*)(crow + (size_t)mm * Ntot + nn) = make_float2(acc[mf][nf][0], acc[mf][nf][1]);
            *(float2*)(crow + (size_t)(mm + 8) * Ntot + nn) = make_float2(acc[mf][nf][2], acc[mf][nf][3]);
        }
    }
}

// ---------------- reductions / final ----------------
__global__ void __launch_bounds__(256) reduce0_kernel(const float* __restrict__ bias) {
    int f = blockIdx.x * 256 + threadIdx.x;   // float4 index, 262144 total
    const float4* p = (const float4*)g_part0;
    float4 b = ((const float4*)bias)[f & 255];
    float sx = b.x, sy = b.y, sz = b.z, sw = b.w;
    #pragma unroll
    for (int i = 0; i < S0; i++) {
        float4 a = p[f + (size_t)i * 262144];
        sx += a.x; sy += a.y; sz += a.z; sw += a.w;
    }
    uint2 o;
    o.x = pack_h2(fmaxf(sx, 0.f), fmaxf(sy, 0.f));
    o.y = pack_h2(fmaxf(sz, 0.f), fmaxf(sw, 0.f));
    ((uint2*)g_h0h)[f] = o;
}

__global__ void __launch_bounds__(256) reduce1_kernel(const float* __restrict__ bias) {
    int f = blockIdx.x * 256 + threadIdx.x;   // float4 index, 131072 total
    const float4* p = (const float4*)g_part1;
    float4 b = ((const float4*)bias)[f & 127];
    float sx = b.x, sy = b.y, sz = b.z, sw = b.w;
    #pragma unroll
    for (int i = 0; i < S1; i++) {
        float4 a = p[f + (size_t)i * 131072];
        sx += a.x; sy += a.y; sz += a.z; sw += a.w;
    }
    float4 o;
    o.x = fmaxf(sx, 0.f); o.y = fmaxf(sy, 0.f);
    o.z = fmaxf(sz, 0.f); o.w = fmaxf(sw, 0.f);
    ((float4*)g_h1)[f] = o;
}

__global__ void __launch_bounds__(256) fc2_kernel(const float* __restrict__ w,
                                                  const float* __restrict__ bias,
                                                  float* __restrict__ out) {
    int wid = threadIdx.x >> 5, lane = threadIdx.x & 31;
    int row = blockIdx.x * 8 + wid;
    const float4* h = (const float4*)(g_h1 + (size_t)row * H2);
    const float4* wv = (const float4*)w;
    float s = 0.f;
    #pragma unroll
    for (int q = 0; q < 4; q++) {
        float4 a = h[lane + q * 32], b = wv[lane + q * 32];
        s += a.x * b.x + a.y * b.y + a.z * b.z + a.w * b.w;
    }
    #pragma unroll
    for (int o = 16; o; o >>= 1) s += __shfl_xor_sync(0xffffffffu, s, o);
    if (lane == 0) out[row] = 1.0f / (1.0f + expf(-(s + bias[0])));
}

// ---------------- launch ----------------
extern "C" void kernel_launch(void* const* d_in, const int* in_sizes, int n_in,
                              void* d_out, int out_size) {
    const float* x    = (const float*)d_in[0];
    const float* W1   = (const float*)d_in[1];
    const float* W2   = (const float*)d_in[2];
    const float* sw1  = (const float*)d_in[3];
    const float* sw2  = (const float*)d_in[4];
    const float* fc0w = (const float*)d_in[5];
    const float* fc0b = (const float*)d_in[6];
    const float* fc1w = (const float*)d_in[7];
    const float* fc1b = (const float*)d_in[8];
    const float* fc2w = (const float*)d_in[9];
    const float* fc2b = (const float*)d_in[10];
    float* out = (float*)d_out;

    __half* w0h;  cudaGetSymbolAddress((void**)&w0h, g_w0h);
    __half* w1h;  cudaGetSymbolAddress((void**)&w1h, g_w1h);
    __half* feat; cudaGetSymbolAddress((void**)&feat, g_feat);
    __half* h0h;  cudaGetSymbolAddress((void**)&h0h, g_h0h);
    float* part0; cudaGetSymbolAddress((void**)&part0, g_part0);
    float* part1; cudaGetSymbolAddress((void**)&part1, g_part1);

    cudaFuncSetAttribute(gemm_kernel, cudaFuncAttributeMaxDynamicSharedMemorySize, SMEM_DYN);

    se_kernel<<<BATCH + 1, 256>>>(x, sw1, sw2);                      // #1 (+pair init)
    tfield_kernel<<<dim3(31, BATCH / 16, 2), 256>>>(x, W1, W2);      // #2
    prep_kernel<<<PREP_FEAT + PREP_W0B + PREP_W1B, 256>>>(x, fc0w, fc1w); // #3
    gemm_kernel<<<8 * 8 * S0, 256, SMEM_DYN>>>(feat, w0h, part0, H1, KTOT, S0); // #4 <- profiled
    reduce0_kernel<<<1024, 256>>>(fc0b);
    gemm_kernel<<<8 * 4 * S1, 256, SMEM_DYN>>>(h0h, w1h, part1, H2, H1, S1);
    reduce1_kernel<<<512, 256>>>(fc1b);
    fc2_kernel<<<BATCH / 8, 256>>>(fc2w, fc2b, out);
}

// round 17
// speedup vs baseline: 1.5000x; 1.0082x over previous
#include <cuda_runtime.h>
#include <cuda_fp16.h>
#include <cstdint>
#include <cstddef>

#define DI __device__ __forceinline__

#define BATCH 1024
#define NF    32
#define NPAIR 496
#define T_LD  1984
#define X_LD  2048
#define HALFK 31744
#define KTOT  63488
#define H1    1024
#define H2    512
#define S0    16                 // fc0 split-K
#define S1    8                  // fc1 split-K

// GEMM tile: BM=128, BN=128, BK=64, 256 threads (8 warps: 2 warp-rows x 4 warp-cols,
// warp tile 64x32). fp16 operands in smem, row stride 72 halves (144B) -> conflict-free
// scalar LDS feed (bank = 4*mlane + klane mod 32, all distinct). 2-stage cp.async pipeline.
#define SROWH 72
#define SROWB 144
#define TBUFH_BYTES (128*SROWB)  // 18432
#define SMEM_DYN (4*TBUFH_BYTES) // 73728

__device__ float  g_x2[BATCH*X_LD];
__device__ __half g_Th[2*BATCH*T_LD];            // bilinear-transformed fields, fp16 (8MB)
__device__ __half g_feat[(size_t)BATCH*KTOT];    // materialized bilinear features (130MB)
__device__ __half g_w0h[(size_t)H1*KTOT];        // fp16 fc0 weights (130MB)
__device__ __half g_w1h[H2*H1];
__device__ __half g_part0h[(size_t)S0*BATCH*H1]; // 32MB fp16 partials
__device__ __half g_h0h[BATCH*H1];
__device__ __half g_part1h[(size_t)S1*BATCH*H2]; // 8MB fp16 partials
__device__ int    g_pi[NPAIR];
__device__ int    g_pj[NPAIR];

DI uint32_t smem_u32(const void* p) {
    uint32_t a;
    asm("{ .reg .u64 t; cvta.to.shared.u64 t, %1; cvt.u32.u64 %0, t; }" : "=r"(a) : "l"(p));
    return a;
}

DI void cp_async16(uint32_t dst, const void* src) {
    asm volatile("cp.async.cg.shared.global [%0], [%1], 16;" :: "r"(dst), "l"(src));
}
#define CP_COMMIT() asm volatile("cp.async.commit_group;" ::: "memory")
#define CP_WAIT0()  asm volatile("cp.async.wait_group 0;" ::: "memory")

DI void mma_f16(float* d, const uint32_t* a, const uint32_t* b) {
    asm volatile(
        "mma.sync.aligned.m16n8k16.row.col.f32.f16.f16.f32 "
        "{%0,%1,%2,%3}, {%4,%5,%6,%7}, {%8,%9}, {%0,%1,%2,%3};"
        : "+f"(d[0]), "+f"(d[1]), "+f"(d[2]), "+f"(d[3])
        : "r"(a[0]), "r"(a[1]), "r"(a[2]), "r"(a[3]), "r"(b[0]), "r"(b[1]));
}

DI uint32_t pack_h2(float a, float b) {
    __half2 h = __floats2half2_rn(a, b);
    return *(uint32_t*)&h;
}
DI float2 unpack_h2(uint32_t u) {
    return __half22float2(*(__half2*)&u);
}

// ---------------- SE block (+pair-table init in the extra block) ----------------
__global__ void __launch_bounds__(256) se_kernel(const float* __restrict__ x,
                                                 const float* __restrict__ w1,
                                                 const float* __restrict__ w2) {
    if (blockIdx.x == BATCH) {
        if (threadIdx.x == 0) {
            int idx = 0;
            for (int i = 0; i < NF - 1; i++)
                for (int j = i + 1; j < NF; j++) { g_pi[idx] = i; g_pj[idx] = j; idx++; }
        }
        return;
    }
    __shared__ float xs[X_LD];
    __shared__ float Zs[NF], A1s[4], A2s[NF];
    int b = blockIdx.x, tid = threadIdx.x;
    const float4* xr = (const float4*)(x + (size_t)b * X_LD);
    float4* xs4 = (float4*)xs;
    xs4[tid] = xr[tid];
    xs4[tid + 256] = xr[tid + 256];
    __syncthreads();
    int wid = tid >> 5, lane = tid & 31;
    #pragma unroll
    for (int ff = 0; ff < 4; ff++) {
        int f = wid * 4 + ff;
        float v = xs[f * 64 + lane] + xs[f * 64 + 32 + lane];
        #pragma unroll
        for (int o = 16; o; o >>= 1) v += __shfl_xor_sync(0xffffffffu, v, o);
        if (lane == 0) Zs[f] = v * (1.0f / 64.0f);
    }
    __syncthreads();
    if (tid < 4) {
        float a = 0.f;
        #pragma unroll
        for (int f = 0; f < NF; f++) a += Zs[f] * w1[tid * NF + f];
        A1s[tid] = fmaxf(a, 0.0f);
    }
    __syncthreads();
    if (tid < NF) {
        float a = 0.f;
        #pragma unroll
        for (int r = 0; r < 4; r++) a += A1s[r] * w2[tid * 4 + r];
        A2s[tid] = 1.0f / (1.0f + expf(-a));
    }
    __syncthreads();
    float4* o4 = (float4*)(g_x2 + (size_t)b * X_LD);
    #pragma unroll
    for (int q = 0; q < 2; q++) {
        int i = tid + q * 256;
        float4 v = xs4[i];
        float sc = A2s[i >> 4];
        v.x *= sc; v.y *= sc; v.z *= sc; v.w *= sc;
        o4[i] = v;
    }
}

// t[v][b][i*64+o] = sum_e feats_v[b,i,e] * W_v[i,o,e]  (output fp16)
__global__ void __launch_bounds__(256) tfield_kernel(const float* __restrict__ x,
                                                     const float* __restrict__ W1,
                                                     const float* __restrict__ W2) {
    __shared__ float Ws[64 * 68];
    __shared__ float xs[16 * 68];
    __shared__ float ts[1024];
    int v = blockIdx.z, fi = blockIdx.x, b0 = blockIdx.y * 16;
    int tid = threadIdx.x;
    const float* W = (v ? W2 : W1) + (size_t)fi * 4096;
    for (int idx = tid; idx < 4096; idx += 256)
        Ws[(idx >> 6) * 68 + (idx & 63)] = W[idx];
    const float* xsrc = (v ? g_x2 : x) + (size_t)b0 * X_LD + fi * 64;
    for (int idx = tid; idx < 1024; idx += 256)
        xs[(idx >> 6) * 68 + (idx & 63)] = xsrc[(size_t)(idx >> 6) * X_LD + (idx & 63)];
    __syncthreads();
    int o = tid >> 2, bg = tid & 3;
    float s0 = 0.f, s1 = 0.f, s2 = 0.f, s3 = 0.f;
    const float4* wrow = (const float4*)(Ws + o * 68);
    #pragma unroll
    for (int e4 = 0; e4 < 16; e4++) {
        float4 wv = wrow[e4];
        float4 a0 = *(const float4*)(xs + (bg * 4 + 0) * 68 + e4 * 4);
        float4 a1 = *(const float4*)(xs + (bg * 4 + 1) * 68 + e4 * 4);
        float4 a2 = *(const float4*)(xs + (bg * 4 + 2) * 68 + e4 * 4);
        float4 a3 = *(const float4*)(xs + (bg * 4 + 3) * 68 + e4 * 4);
        s0 += wv.x*a0.x + wv.y*a0.y + wv.z*a0.z + wv.w*a0.w;
        s1 += wv.x*a1.x + wv.y*a1.y + wv.z*a1.z + wv.w*a1.w;
        s2 += wv.x*a2.x + wv.y*a2.y + wv.z*a2.z + wv.w*a2.w;
        s3 += wv.x*a3.x + wv.y*a3.y + wv.z*a3.z + wv.w*a3.w;
    }
    ts[(bg * 4 + 0) * 64 + o] = s0;
    ts[(bg * 4 + 1) * 64 + o] = s1;
    ts[(bg * 4 + 2) * 64 + o] = s2;
    ts[(bg * 4 + 3) * 64 + o] = s3;
    __syncthreads();
    __half* trow = g_Th + (size_t)v * (BATCH * T_LD);
    for (int idx = tid; idx < 512; idx += 256) {
        int r = idx >> 5, c2 = idx & 31;
        float2 tv = *(const float2*)(ts + r * 64 + c2 * 2);
        uint32_t h = pack_h2(tv.x, tv.y);
        *(uint32_t*)(trow + (size_t)(b0 + r) * T_LD + fi * 64 + c2 * 2) = h;
    }
}

// ---------------- fused prep: featgen + fc0 weight f2h + fc1 weight f2h ----------------
#define PREP_FEAT   31744
#define PREP_W0B    15872
#define PREP_W1B    128
__global__ void __launch_bounds__(256) prep_kernel(const float* __restrict__ x,
                                                   const float* __restrict__ fc0w,
                                                   const float* __restrict__ fc1w) {
    int blk = blockIdx.x;
    int tid = threadIdx.x;
    if (blk < PREP_FEAT) {
        int p = blk % NPAIR;
        int rest = blk / NPAIR;
        int b0 = (rest & 31) * 32;
        int v = rest >> 5;
        int r = tid >> 3, ec = (tid & 7) * 8;
        int ip = g_pi[p], jp = g_pj[p];
        int b = b0 + r;
        const __half* tb = g_Th + (size_t)v * (BATCH * T_LD) + (size_t)b * T_LD + ip * 64 + ec;
        const float*  xb = (v ? g_x2 : x) + (size_t)b * X_LD + jp * 64 + ec;
        uint4 th = *(const uint4*)tb;
        float4 x0 = *(const float4*)xb, x1 = *(const float4*)(xb + 4);
        float2 t0 = unpack_h2(th.x), t1 = unpack_h2(th.y);
        float2 t2 = unpack_h2(th.z), t3 = unpack_h2(th.w);
        uint4 o;
        o.x = pack_h2(t0.x * x0.x, t0.y * x0.y);
        o.y = pack_h2(t1.x * x0.z, t1.y * x0.w);
        o.z = pack_h2(t2.x * x1.x, t2.y * x1.y);
        o.w = pack_h2(t3.x * x1.z, t3.y * x1.w);
        *(uint4*)(g_feat + (size_t)b * KTOT + v * HALFK + p * 64 + ec) = o;
    } else if (blk < PREP_FEAT + PREP_W0B) {
        size_t base = (size_t)(blk - PREP_FEAT) * 1024 + tid;
        float4 v0 = ((const float4*)fc0w)[base];
        float4 v1 = ((const float4*)fc0w)[base + 256];
        float4 v2 = ((const float4*)fc0w)[base + 512];
        float4 v3 = ((const float4*)fc0w)[base + 768];
        uint2 o0, o1, o2, o3;
        o0.x = pack_h2(v0.x, v0.y); o0.y = pack_h2(v0.z, v0.w);
        o1.x = pack_h2(v1.x, v1.y); o1.y = pack_h2(v1.z, v1.w);
        o2.x = pack_h2(v2.x, v2.y); o2.y = pack_h2(v2.z, v2.w);
        o3.x = pack_h2(v3.x, v3.y); o3.y = pack_h2(v3.z, v3.w);
        ((uint2*)g_w0h)[base] = o0;
        ((uint2*)g_w0h)[base + 256] = o1;
        ((uint2*)g_w0h)[base + 512] = o2;
        ((uint2*)g_w0h)[base + 768] = o3;
    } else {
        size_t base = (size_t)(blk - PREP_FEAT - PREP_W0B) * 1024 + tid;
        float4 v0 = ((const float4*)fc1w)[base];
        float4 v1 = ((const float4*)fc1w)[base + 256];
        float4 v2 = ((const float4*)fc1w)[base + 512];
        float4 v3 = ((const float4*)fc1w)[base + 768];
        uint2 o0, o1, o2, o3;
        o0.x = pack_h2(v0.x, v0.y); o0.y = pack_h2(v0.z, v0.w);
        o1.x = pack_h2(v1.x, v1.y); o1.y = pack_h2(v1.z, v1.w);
        o2.x = pack_h2(v2.x, v2.y); o2.y = pack_h2(v2.z, v2.w);
        o3.x = pack_h2(v3.x, v3.y); o3.y = pack_h2(v3.z, v3.w);
        ((uint2*)g_w1h)[base] = o0;
        ((uint2*)g_w1h)[base + 256] = o1;
        ((uint2*)g_w1h)[base + 512] = o2;
        ((uint2*)g_w1h)[base + 768] = o3;
    }
}

// ---------------- mma.sync fp16 GEMM (BK=64, 2-stage cp.async, interleaved feed) ----------------
// C[m,n] = sum_k A[m,k] * W[n,k]; partials stored fp16.
// CTA decode: mb fastest, then nb, then s -> one s-group's CTAs co-resident in L2.
__global__ void __launch_bounds__(256, 2) gemm_kernel(const __half* __restrict__ Ah,
                                                      const __half* __restrict__ Bw,
                                                      __half* __restrict__ Cpart,
                                                      int Ntot, int Ktot, int S) {
    extern __shared__ char smc[];
    uint32_t smb = smem_u32(smc);
    int tid = threadIdx.x;
    int w = tid >> 5, l = tid & 31;
    int wr = w >> 2, wc = w & 3;
    int nbn = Ntot >> 7;
    int mb = blockIdx.x % 8;
    int nb = (blockIdx.x / 8) % nbn;
    int s  = blockIdx.x / (8 * nbn);
    int m0 = mb * 128, n0 = nb * 128;
    int Kper = Ktot / S;
    int k_base = s * Kper;
    int ntiles = Kper >> 6;

    int cr = tid >> 2, cq = tid & 3;

    float acc[4][4][4];
    #pragma unroll
    for (int i = 0; i < 4; i++)
        #pragma unroll
        for (int j = 0; j < 4; j++)
            #pragma unroll
            for (int q = 0; q < 4; q++) acc[i][j][q] = 0.f;

    auto cp_tile = [&](int kg, int st) {
        uint32_t baseA = smb + st * 2 * TBUFH_BYTES;
        uint32_t baseB = baseA + TBUFH_BYTES;
        #pragma unroll
        for (int it = 0; it < 2; it++) {
            int r = cr + it * 64;
            const __half* arow = Ah + (size_t)(m0 + r) * Ktot + kg;
            const __half* brow = Bw + (size_t)(n0 + r) * Ktot + kg;
            uint32_t dA = baseA + r * SROWB;
            uint32_t dB = baseB + r * SROWB;
            #pragma unroll
            for (int c = 0; c < 2; c++) {
                int ch = cq + c * 4;
                cp_async16(dA + ch * 16, arow + ch * 8);
                cp_async16(dB + ch * 16, brow + ch * 8);
            }
        }
    };

    cp_tile(k_base, 0);
    CP_COMMIT();

    int mlane = l >> 2, klane = l & 3;
    for (int kt = 0; kt < ntiles; kt++) {
        int st = kt & 1;
        CP_WAIT0();
        __syncthreads();
        if (kt + 1 < ntiles) {
            cp_tile(k_base + ((kt + 1) << 6), st ^ 1);
            CP_COMMIT();
        }

        const uint32_t* uA = (const uint32_t*)(smc + st * 2 * TBUFH_BYTES);
        const uint32_t* uB = (const uint32_t*)(smc + st * 2 * TBUFH_BYTES + TBUFH_BYTES);
        #pragma unroll
        for (int ks = 0; ks < 4; ks++) {
            int kw = ks * 8 + klane;
            uint32_t afr[4][4];
            #pragma unroll
            for (int mf = 0; mf < 4; mf++) {
                int m = wr * 64 + mf * 16 + mlane;
                afr[mf][0] = uA[m * 36 + kw];
                afr[mf][1] = uA[(m + 8) * 36 + kw];
                afr[mf][2] = uA[m * 36 + kw + 4];
                afr[mf][3] = uA[(m + 8) * 36 + kw + 4];
            }
            #pragma unroll
            for (int nf = 0; nf < 4; nf++) {
                int n = wc * 32 + nf * 8 + mlane;
                uint32_t bfr[2];
                bfr[0] = uB[n * 36 + kw];
                bfr[1] = uB[n * 36 + kw + 4];
                #pragma unroll
                for (int mf = 0; mf < 4; mf++)
                    mma_f16(acc[mf][nf], afr[mf], bfr);
            }
        }
    }

    __half* crow = Cpart + ((size_t)s * BATCH + m0 + wr * 64) * Ntot + n0 + wc * 32;
    #pragma unroll
    for (int mf = 0; mf < 4; mf++) {
        int mm = mf * 16 + (l >> 2);
        #pragma unroll
        for (int nf = 0; nf < 4; nf++) {
            int nn = nf * 8 + (l & 3) * 2;
            *(uint32_t*)(crow + (size_t)mm * Ntot + nn) = pack_h2(acc[mf][nf][0], acc[mf][nf][1]);
            *(uint32_t*)(crow + (size_t)(mm + 8) * Ntot + nn) = pack_h2(acc[mf][nf][2], acc[mf][nf][3]);
        }
    }
}

// ---------------- reductions / final ----------------
__global__ void __launch_bounds__(256) reduce0_kernel(const float* __restrict__ bias) {
    int f = blockIdx.x * 256 + threadIdx.x;   // uint2 index (4 halves), 262144 total
    const uint2* p = (const uint2*)g_part0h;
    float4 b = ((const float4*)bias)[f & 255];
    float sx = b.x, sy = b.y, sz = b.z, sw = b.w;
    #pragma unroll
    for (int i = 0; i < S0; i++) {
        uint2 a = p[f + (size_t)i * 262144];
        float2 lo = unpack_h2(a.x), hi = unpack_h2(a.y);
        sx += lo.x; sy += lo.y; sz += hi.x; sw += hi.y;
    }
    uint2 o;
    o.x = pack_h2(fmaxf(sx, 0.f), fmaxf(sy, 0.f));
    o.y = pack_h2(fmaxf(sz, 0.f), fmaxf(sw, 0.f));
    ((uint2*)g_h0h)[f] = o;
}

// merged reduce1 + fc2: block per batch row (128 threads, 4 cols each)
__global__ void __launch_bounds__(128) reduce1_fc2_kernel(const float* __restrict__ bias1,
                                                          const float* __restrict__ w2,
                                                          const float* __restrict__ bias2,
                                                          float* __restrict__ out) {
    __shared__ float warp_sums[4];
    int b = blockIdx.x, t = threadIdx.x;
    const uint2* p = (const uint2*)g_part1h;
    float4 bv = ((const float4*)bias1)[t];
    float s0 = bv.x, s1 = bv.y, s2 = bv.z, s3 = bv.w;
    #pragma unroll
    for (int i = 0; i < S1; i++) {
        uint2 a = p[(size_t)(i * BATCH + b) * 128 + t];
        float2 lo = unpack_h2(a.x), hi = unpack_h2(a.y);
        s0 += lo.x; s1 += lo.y; s2 += hi.x; s3 += hi.y;
    }
    s0 = fmaxf(s0, 0.f); s1 = fmaxf(s1, 0.f);
    s2 = fmaxf(s2, 0.f); s3 = fmaxf(s3, 0.f);
    float4 wv = ((const float4*)w2)[t];
    float d = s0 * wv.x + s1 * wv.y + s2 * wv.z + s3 * wv.w;
    #pragma unroll
    for (int o = 16; o; o >>= 1) d += __shfl_xor_sync(0xffffffffu, d, o);
    if ((t & 31) == 0) warp_sums[t >> 5] = d;
    __syncthreads();
    if (t == 0) {
        float tot = warp_sums[0] + warp_sums[1] + warp_sums[2] + warp_sums[3] + bias2[0];
        out[b] = 1.0f / (1.0f + expf(-tot));
    }
}

// ---------------- launch ----------------
extern "C" void kernel_launch(void* const* d_in, const int* in_sizes, int n_in,
                              void* d_out, int out_size) {
    const float* x    = (const float*)d_in[0];
    const float* W1   = (const float*)d_in[1];
    const float* W2   = (const float*)d_in[2];
    const float* sw1  = (const float*)d_in[3];
    const float* sw2  = (const float*)d_in[4];
    const float* fc0w = (const float*)d_in[5];
    const float* fc0b = (const float*)d_in[6];
    const float* fc1w = (const float*)d_in[7];
    const float* fc1b = (const float*)d_in[8];
    const float* fc2w = (const float*)d_in[9];
    const float* fc2b = (const float*)d_in[10];
    float* out = (float*)d_out;

    __half* w0h;  cudaGetSymbolAddress((void**)&w0h, g_w0h);
    __half* w1h;  cudaGetSymbolAddress((void**)&w1h, g_w1h);
    __half* feat; cudaGetSymbolAddress((void**)&feat, g_feat);
    __half* h0h;  cudaGetSymbolAddress((void**)&h0h, g_h0h);
    __half* part0; cudaGetSymbolAddress((void**)&part0, g_part0h);
    __half* part1; cudaGetSymbolAddress((void**)&part1, g_part1h);

    cudaFuncSetAttribute(gemm_kernel, cudaFuncAttributeMaxDynamicSharedMemorySize, SMEM_DYN);

    se_kernel<<<BATCH + 1, 256>>>(x, sw1, sw2);                      // #1 (+pair init)
    tfield_kernel<<<dim3(31, BATCH / 16, 2), 256>>>(x, W1, W2);      // #2
    prep_kernel<<<PREP_FEAT + PREP_W0B + PREP_W1B, 256>>>(x, fc0w, fc1w); // #3
    gemm_kernel<<<8 * 8 * S0, 256, SMEM_DYN>>>(feat, w0h, part0, H1, KTOT, S0); // #4 <- profiled
    reduce0_kernel<<<1024, 256>>>(fc0b);
    gemm_kernel<<<8 * 4 * S1, 256, SMEM_DYN>>>(h0h, w1h, part1, H2, H1, S1);
    reduce1_fc2_kernel<<<BATCH, 128>>>(fc1b, fc2w, fc2b, out);
}